// round 1
// baseline (speedup 1.0000x reference)
#include <cuda_runtime.h>
#include <cuda_bf16.h>
#include <math.h>

#define BATCH   2
#define SEQ     2048
#define HIDDEN  2048
#define NH      16
#define NKV     4
#define HD      128
#define MTOT    (BATCH*SEQ)      // 4096
#define QDIM    (NH*HD)          // 2048
#define KVDIM   (NKV*HD)         // 512
#define ATTN_SCALE 0.08838834764831845f  // 128^-0.5
#define NEGBIG  -1000000000.0f

// ---------------- scratch (device globals; no allocation allowed) ----------
__device__ float g_Q[(size_t)MTOT*QDIM];            // 33.5 MB
__device__ float g_K[(size_t)MTOT*KVDIM];           // 8.4 MB
__device__ float g_V[(size_t)MTOT*KVDIM];           // 8.4 MB
__device__ float g_S[(size_t)BATCH*NH*SEQ*SEQ];     // 537 MB scores/probs
__device__ float g_AO[(size_t)MTOT*QDIM];           // 33.5 MB

// ---------------- 128x128 fp32 GEMM mainloop (BK=16, 256 thr, 8x8/thread) --
// NT=true : B is [N,K] row-major (C = A @ B^T)
// NT=false: B is [K,N] row-major (C = A @ B)
template<bool NT>
__device__ __forceinline__ void gemm_mainloop(const float* __restrict__ A, int lda,
                                              const float* __restrict__ B, int ldb,
                                              int K, float acc[8][8])
{
    __shared__ float As[16][128];
    __shared__ float Bs[16][128];
    const int tid = threadIdx.x;
    const int ar = tid >> 2;            // 0..63
    const int ak = (tid & 3) << 2;      // 0,4,8,12
    const int bk = tid >> 5;            // 0..7
    const int bn = (tid & 31) << 2;     // 0..124
    const int ty = (tid >> 4) << 3;
    const int tx = (tid & 15) << 3;

    for (int k0 = 0; k0 < K; k0 += 16) {
        float4 a0 = *(const float4*)(A + (size_t)ar      * lda + k0 + ak);
        float4 a1 = *(const float4*)(A + (size_t)(ar+64) * lda + k0 + ak);
        As[ak+0][ar] = a0.x; As[ak+1][ar] = a0.y; As[ak+2][ar] = a0.z; As[ak+3][ar] = a0.w;
        As[ak+0][ar+64] = a1.x; As[ak+1][ar+64] = a1.y; As[ak+2][ar+64] = a1.z; As[ak+3][ar+64] = a1.w;
        if (NT) {
            float4 b0 = *(const float4*)(B + (size_t)ar      * ldb + k0 + ak);
            float4 b1 = *(const float4*)(B + (size_t)(ar+64) * ldb + k0 + ak);
            Bs[ak+0][ar] = b0.x; Bs[ak+1][ar] = b0.y; Bs[ak+2][ar] = b0.z; Bs[ak+3][ar] = b0.w;
            Bs[ak+0][ar+64] = b1.x; Bs[ak+1][ar+64] = b1.y; Bs[ak+2][ar+64] = b1.z; Bs[ak+3][ar+64] = b1.w;
        } else {
            float4 b0 = *(const float4*)(B + (size_t)(k0+bk)   * ldb + bn);
            float4 b1 = *(const float4*)(B + (size_t)(k0+bk+8) * ldb + bn);
            *(float4*)&Bs[bk  ][bn] = b0;
            *(float4*)&Bs[bk+8][bn] = b1;
        }
        __syncthreads();
        #pragma unroll
        for (int kk = 0; kk < 16; kk++) {
            float a[8], b[8];
            *(float4*)&a[0] = *(const float4*)&As[kk][ty];
            *(float4*)&a[4] = *(const float4*)&As[kk][ty+4];
            *(float4*)&b[0] = *(const float4*)&Bs[kk][tx];
            *(float4*)&b[4] = *(const float4*)&Bs[kk][tx+4];
            #pragma unroll
            for (int i = 0; i < 8; i++)
                #pragma unroll
                for (int j = 0; j < 8; j++)
                    acc[i][j] = fmaf(a[i], b[j], acc[i][j]);
        }
        __syncthreads();
    }
}

__device__ __forceinline__ void store_tile(float* C, int ldc, float acc[8][8])
{
    const int tid = threadIdx.x;
    const int ty = (tid >> 4) << 3, tx = (tid & 15) << 3;
    #pragma unroll
    for (int i = 0; i < 8; i++) {
        *(float4*)(C + (size_t)(ty+i)*ldc + tx    ) = make_float4(acc[i][0],acc[i][1],acc[i][2],acc[i][3]);
        *(float4*)(C + (size_t)(ty+i)*ldc + tx + 4) = make_float4(acc[i][4],acc[i][5],acc[i][6],acc[i][7]);
    }
}

// ---------------- generic NT GEMM: C[M,N] = A[M,K] @ B[N,K]^T ---------------
__global__ void k_gemm_nt(const float* __restrict__ A, int lda,
                          const float* __restrict__ B, int ldb,
                          float* __restrict__ C, int ldc, int K)
{
    float acc[8][8];
    #pragma unroll
    for (int i = 0; i < 8; i++)
        #pragma unroll
        for (int j = 0; j < 8; j++) acc[i][j] = 0.f;
    gemm_mainloop<true>(A + (size_t)blockIdx.y*128*lda, lda,
                        B + (size_t)blockIdx.x*128*ldb, ldb, K, acc);
    store_tile(C + (size_t)blockIdx.y*128*ldc + blockIdx.x*128, ldc, acc);
}

// ---------------- RoPE on Q ------------------------------------------------
__global__ void k_rope_q(const float* __restrict__ freqs)
{
    int idx = blockIdx.x*blockDim.x + threadIdx.x;  // total MTOT*NH*64
    int i = idx & 63;
    int h = (idx >> 6) & (NH-1);
    int m = idx >> 10;
    int s = m & (SEQ-1);
    float f = freqs[(size_t)s*64 + i];
    float sn, cs; sincosf(f, &sn, &cs);
    float* p = g_Q + (size_t)m*QDIM + h*HD + 2*i;
    float2 v = *(float2*)p;
    float2 r;
    r.x = v.x*cs - v.y*sn;
    r.y = v.x*sn + v.y*cs;
    *(float2*)p = r;
}

// ---------------- RoPE on K + emit new_k -----------------------------------
__global__ void k_rope_k(const float* __restrict__ freqs, float* __restrict__ outk)
{
    int idx = blockIdx.x*blockDim.x + threadIdx.x;  // total MTOT*NKV*64
    int i = idx & 63;
    int h = (idx >> 6) & (NKV-1);
    int m = idx >> 8;
    int s = m & (SEQ-1);
    float f = freqs[(size_t)s*64 + i];
    float sn, cs; sincosf(f, &sn, &cs);
    size_t off = (size_t)m*KVDIM + h*HD + 2*i;
    float2 v = *(float2*)(g_K + off);
    float2 r;
    r.x = v.x*cs - v.y*sn;
    r.y = v.x*sn + v.y*cs;
    *(float2*)(g_K + off) = r;
    *(float2*)(outk + off) = r;
}

// ---------------- copy V -> new_v -------------------------------------------
__global__ void k_copy_v(float* __restrict__ outv)
{
    int idx = blockIdx.x*blockDim.x + threadIdx.x;   // MTOT*KVDIM/4 threads
    float4 v = *((const float4*)g_V + idx);
    *((float4*)outv + idx) = v;
}

// ---------------- scores: S[bh,q,k] = scale * Q·K^T, causal tiles only ------
__global__ void k_scores()
{
    const int qt = blockIdx.x, kt = blockIdx.y, bh = blockIdx.z;
    if (kt > qt) return;                        // above-diagonal tiles never read
    const int b = bh >> 4, h = bh & 15, kh = h >> 2;
    const float* A = g_Q + ((size_t)(b*SEQ + qt*128))*QDIM  + h*HD;
    const float* B = g_K + ((size_t)(b*SEQ + kt*128))*KVDIM + kh*HD;
    float acc[8][8];
    #pragma unroll
    for (int i = 0; i < 8; i++)
        #pragma unroll
        for (int j = 0; j < 8; j++) acc[i][j] = 0.f;
    gemm_mainloop<true>(A, QDIM, B, KVDIM, HD, acc);

    float* C = g_S + (size_t)bh*SEQ*SEQ + (size_t)qt*128*SEQ + kt*128;
    const int tid = threadIdx.x;
    const int ty = (tid >> 4) << 3, tx = (tid & 15) << 3;
    const int qg0 = qt*128 + ty, kg0 = kt*128 + tx;
    #pragma unroll
    for (int i = 0; i < 8; i++)
        #pragma unroll
        for (int j = 0; j < 8; j++) {
            float v = acc[i][j] * ATTN_SCALE;
            if (kg0 + j > qg0 + i) v = NEGBIG;      // causal mask
            C[(size_t)(ty+i)*SEQ + tx + j] = v;
        }
}

// ---------------- row softmax over valid causal extent ----------------------
__global__ void k_softmax()
{
    const int q = blockIdx.x, bh = blockIdx.y;
    float* row = g_S + (size_t)bh*SEQ*SEQ + (size_t)q*SEQ;
    const int len = q + 1;
    const int pad = ((q >> 7) + 1) << 7;   // 128-aligned end read by PV
    const int tid = threadIdx.x;
    __shared__ float red[256];

    float m = -1e30f;
    for (int k = tid; k < len; k += 256) m = fmaxf(m, row[k]);
    red[tid] = m; __syncthreads();
    for (int off = 128; off; off >>= 1) {
        if (tid < off) red[tid] = fmaxf(red[tid], red[tid+off]);
        __syncthreads();
    }
    m = red[0]; __syncthreads();

    float s = 0.f;
    for (int k = tid; k < len; k += 256) {
        float e = __expf(row[k] - m);
        row[k] = e;
        s += e;
    }
    red[tid] = s; __syncthreads();
    for (int off = 128; off; off >>= 1) {
        if (tid < off) red[tid] += red[tid+off];
        __syncthreads();
    }
    const float inv = 1.0f / red[0];
    for (int k = tid; k < len; k += 256) row[k] *= inv;
    for (int k = len + tid; k < pad; k += 256) row[k] = 0.f;   // zero-fill diag tile tail
}

// ---------------- PV: AO = P @ V, K-loop bounded by causal extent -----------
__global__ void k_pv()
{
    const int qt = blockIdx.x, bh = blockIdx.y;
    const int b = bh >> 4, h = bh & 15, kh = h >> 2;
    const int K = (qt + 1) * 128;
    const float* A = g_S + (size_t)bh*SEQ*SEQ + (size_t)qt*128*SEQ;
    const float* B = g_V + (size_t)(b*SEQ)*KVDIM + kh*HD;
    float acc[8][8];
    #pragma unroll
    for (int i = 0; i < 8; i++)
        #pragma unroll
        for (int j = 0; j < 8; j++) acc[i][j] = 0.f;
    gemm_mainloop<false>(A, SEQ, B, KVDIM, K, acc);
    store_tile(g_AO + (size_t)(b*SEQ + qt*128)*QDIM + h*HD, QDIM, acc);
}

// ---------------- launch ----------------------------------------------------
extern "C" void kernel_launch(void* const* d_in, const int* in_sizes, int n_in,
                              void* d_out, int out_size)
{
    const float* x     = (const float*)d_in[0];
    const float* wq    = (const float*)d_in[1];
    const float* wk    = (const float*)d_in[2];
    const float* wv    = (const float*)d_in[3];
    const float* wo    = (const float*)d_in[4];
    const float* freqs = (const float*)d_in[5];
    (void)d_in; (void)in_sizes; (void)n_in; (void)out_size;

    float* out  = (float*)d_out;
    float* outk = out  + (size_t)MTOT*HIDDEN;          // 8,388,608
    float* outv = outk + (size_t)MTOT*KVDIM;           // +2,097,152

    float *Qp, *Kp, *Vp, *AOp;
    cudaGetSymbolAddress((void**)&Qp,  g_Q);
    cudaGetSymbolAddress((void**)&Kp,  g_K);
    cudaGetSymbolAddress((void**)&Vp,  g_V);
    cudaGetSymbolAddress((void**)&AOp, g_AO);

    // 1. projections
    k_gemm_nt<<<dim3(QDIM/128,  MTOT/128), 256>>>(x, HIDDEN, wq, HIDDEN, Qp, QDIM,  HIDDEN);
    k_gemm_nt<<<dim3(KVDIM/128, MTOT/128), 256>>>(x, HIDDEN, wk, HIDDEN, Kp, KVDIM, HIDDEN);
    k_gemm_nt<<<dim3(KVDIM/128, MTOT/128), 256>>>(x, HIDDEN, wv, HIDDEN, Vp, KVDIM, HIDDEN);

    // 2. rope + kv-cache outputs
    k_rope_q<<<(MTOT*NH *64)/256, 256>>>(freqs);
    k_rope_k<<<(MTOT*NKV*64)/256, 256>>>(freqs, outk);
    k_copy_v<<<(MTOT*KVDIM/4)/256, 256>>>(outv);

    // 3-5. attention
    k_scores <<<dim3(SEQ/128, SEQ/128, BATCH*NH), 256>>>();
    k_softmax<<<dim3(SEQ, BATCH*NH), 256>>>();
    k_pv     <<<dim3(SEQ/128, BATCH*NH), 256>>>();

    // 6. output projection
    k_gemm_nt<<<dim3(HIDDEN/128, MTOT/128), 256>>>(AOp, QDIM, wo, HIDDEN, out, HIDDEN, QDIM);
}

// round 3
// speedup vs baseline: 1.6513x; 1.6513x over previous
#include <cuda_runtime.h>
#include <cuda_bf16.h>
#include <math.h>
#include <stdint.h>

#define BATCH   2
#define SEQ     2048
#define HIDDEN  2048
#define NH      16
#define NKV     4
#define HD      128
#define MTOT    (BATCH*SEQ)      // 4096
#define QDIM    (NH*HD)          // 2048
#define KVDIM   (NKV*HD)         // 512
#define QKVDIM  (QDIM+2*KVDIM)   // 3072
#define ATTN_SCALE 0.08838834764831845f
#define NEGBIG  -1000000000.0f

// ---------------- scratch (device globals; no allocation allowed) ----------
__device__ float g_QKV[(size_t)MTOT*QKVDIM];        // 50 MB  (Q | K | V per row)
__device__ float g_S[(size_t)BATCH*NH*SEQ*SEQ];     // 537 MB scores/probs
__device__ float g_AO[(size_t)MTOT*QDIM];           // 33.5 MB
__device__ __nv_bfloat16 g_Xh[(size_t)MTOT*HIDDEN];
__device__ __nv_bfloat16 g_Xl[(size_t)MTOT*HIDDEN];
__device__ __nv_bfloat16 g_Wh[(size_t)QKVDIM*HIDDEN];
__device__ __nv_bfloat16 g_Wl[(size_t)QKVDIM*HIDDEN];
__device__ __nv_bfloat16 g_WOh[(size_t)HIDDEN*QDIM];
__device__ __nv_bfloat16 g_WOl[(size_t)HIDDEN*QDIM];
__device__ __nv_bfloat16 g_AOh[(size_t)MTOT*QDIM];
__device__ __nv_bfloat16 g_AOl[(size_t)MTOT*QDIM];

// ================= HMMA helpers (sm_80-era, legal on sm_103 target) ========
__device__ __forceinline__ void ldsm_x4(uint32_t* r, uint32_t addr) {
    asm volatile("ldmatrix.sync.aligned.m8n8.x4.shared.b16 {%0,%1,%2,%3}, [%4];"
                 : "=r"(r[0]), "=r"(r[1]), "=r"(r[2]), "=r"(r[3]) : "r"(addr));
}
__device__ __forceinline__ void ldsm_x2(uint32_t* r, uint32_t addr) {
    asm volatile("ldmatrix.sync.aligned.m8n8.x2.shared.b16 {%0,%1}, [%2];"
                 : "=r"(r[0]), "=r"(r[1]) : "r"(addr));
}
__device__ __forceinline__ void mma16816(float* d, const uint32_t* a, const uint32_t* b) {
    asm volatile("mma.sync.aligned.m16n8k16.row.col.f32.bf16.bf16.f32 "
                 "{%0,%1,%2,%3},{%4,%5,%6,%7},{%8,%9},{%0,%1,%2,%3};"
                 : "+f"(d[0]), "+f"(d[1]), "+f"(d[2]), "+f"(d[3])
                 : "r"(a[0]), "r"(a[1]), "r"(a[2]), "r"(a[3]), "r"(b[0]), "r"(b[1]));
}
__device__ __forceinline__ uint32_t smem_u32(const void* p) {
    return (uint32_t)__cvta_generic_to_shared(p);
}

// ============ HMMA GEMM: C[M,N](fp32) = (Ah+Al)[M,K] @ (Bh+Bl)[N,K]^T =======
// 128x128 CTA tile, 8 warps (2x4), warp tile 64x32, BK=32, 3-pass bf16 split.
#define BK   32
#define SPAD 8
#define SLD  (BK + SPAD)   // 40 halves per smem row

__global__ void __launch_bounds__(256, 2) mma_gemm(
    const __nv_bfloat16* __restrict__ Ah, const __nv_bfloat16* __restrict__ Al,
    const __nv_bfloat16* __restrict__ Bh, const __nv_bfloat16* __restrict__ Bl,
    float* __restrict__ C, int ldc, int K)
{
    __shared__ __nv_bfloat16 sAh[128][SLD];
    __shared__ __nv_bfloat16 sAl[128][SLD];
    __shared__ __nv_bfloat16 sBh[128][SLD];
    __shared__ __nv_bfloat16 sBl[128][SLD];

    const int tid  = threadIdx.x;
    const int lane = tid & 31;
    const int wid  = tid >> 5;
    const int wr   = wid >> 2;     // 0..1  (64-row slab)
    const int wc   = wid & 3;      // 0..3  (32-col slab)

    float acc[4][4][4];
    #pragma unroll
    for (int m = 0; m < 4; m++)
        #pragma unroll
        for (int n = 0; n < 4; n++)
            #pragma unroll
            for (int i = 0; i < 4; i++) acc[m][n][i] = 0.f;

    const size_t arow0 = (size_t)blockIdx.y * 128;
    const size_t brow0 = (size_t)blockIdx.x * 128;

    // ldmatrix source addresses (fixed per thread; advance cols by kk)
    const int a_r = lane & 15, a_c = ((lane >> 4) & 1) * 8;
    const int b_r = lane & 7,  b_c = ((lane >> 3) & 1) * 8;

    for (int k0 = 0; k0 < K; k0 += BK) {
        // fill 4 smem tiles: 128 rows x 32 halves each (512 uint4 per tile)
        #pragma unroll
        for (int t = 0; t < 2; t++) {
            int idx = tid + t * 256;         // 0..511
            int r = idx >> 2, c = idx & 3;   // row, 8-half chunk
            *(uint4*)&sAh[r][c * 8] = *(const uint4*)(Ah + (arow0 + r) * K + k0 + c * 8);
            *(uint4*)&sAl[r][c * 8] = *(const uint4*)(Al + (arow0 + r) * K + k0 + c * 8);
            *(uint4*)&sBh[r][c * 8] = *(const uint4*)(Bh + (brow0 + r) * K + k0 + c * 8);
            *(uint4*)&sBl[r][c * 8] = *(const uint4*)(Bl + (brow0 + r) * K + k0 + c * 8);
        }
        __syncthreads();

        #pragma unroll
        for (int kk = 0; kk < BK; kk += 16) {
            uint32_t bh[4][2], bl[4][2];
            #pragma unroll
            for (int n = 0; n < 4; n++) {
                int row = wc * 32 + n * 8 + b_r;
                ldsm_x2(bh[n], smem_u32(&sBh[row][kk + b_c]));
                ldsm_x2(bl[n], smem_u32(&sBl[row][kk + b_c]));
            }
            #pragma unroll
            for (int m = 0; m < 4; m++) {
                uint32_t ah[4], al[4];
                int row = wr * 64 + m * 16 + a_r;
                ldsm_x4(ah, smem_u32(&sAh[row][kk + a_c]));
                ldsm_x4(al, smem_u32(&sAl[row][kk + a_c]));
                #pragma unroll
                for (int n = 0; n < 4; n++) {
                    mma16816(acc[m][n], ah, bh[n]);
                    mma16816(acc[m][n], ah, bl[n]);
                    mma16816(acc[m][n], al, bh[n]);
                }
            }
        }
        __syncthreads();
    }

    // epilogue: fp32 accumulators straight to global
    const int r0 = lane >> 2, cbase = (lane & 3) * 2;
    #pragma unroll
    for (int m = 0; m < 4; m++) {
        size_t grow = arow0 + wr * 64 + m * 16 + r0;
        #pragma unroll
        for (int n = 0; n < 4; n++) {
            size_t gcol = brow0 + wc * 32 + n * 8 + cbase;
            *(float2*)(C + grow * ldc + gcol)       = make_float2(acc[m][n][0], acc[m][n][1]);
            *(float2*)(C + (grow + 8) * ldc + gcol) = make_float2(acc[m][n][2], acc[m][n][3]);
        }
    }
}

// ---------------- fp32 -> bf16 hi/lo split ----------------------------------
__global__ void k_split(const float* __restrict__ src, __nv_bfloat16* __restrict__ hi,
                        __nv_bfloat16* __restrict__ lo, int n4)
{
    int i = blockIdx.x * blockDim.x + threadIdx.x;
    if (i >= n4) return;
    float4 v = ((const float4*)src)[i];
    __nv_bfloat16 h0 = __float2bfloat16(v.x), h1 = __float2bfloat16(v.y);
    __nv_bfloat16 h2 = __float2bfloat16(v.z), h3 = __float2bfloat16(v.w);
    __nv_bfloat16 l0 = __float2bfloat16(v.x - __bfloat162float(h0));
    __nv_bfloat16 l1 = __float2bfloat16(v.y - __bfloat162float(h1));
    __nv_bfloat16 l2 = __float2bfloat16(v.z - __bfloat162float(h2));
    __nv_bfloat16 l3 = __float2bfloat16(v.w - __bfloat162float(h3));
    ushort4 hv = make_ushort4(*(unsigned short*)&h0, *(unsigned short*)&h1,
                              *(unsigned short*)&h2, *(unsigned short*)&h3);
    ushort4 lv = make_ushort4(*(unsigned short*)&l0, *(unsigned short*)&l1,
                              *(unsigned short*)&l2, *(unsigned short*)&l3);
    ((ushort4*)hi)[i] = hv;
    ((ushort4*)lo)[i] = lv;
}

// ============ SIMT fp32 GEMM mainloop (used for scores & PV) ================
template<bool NT>
__device__ __forceinline__ void gemm_mainloop(const float* __restrict__ A, int lda,
                                              const float* __restrict__ B, int ldb,
                                              int K, float acc[8][8])
{
    __shared__ float As[16][128];
    __shared__ float Bs[16][128];
    const int tid = threadIdx.x;
    const int ar = tid >> 2;
    const int ak = (tid & 3) << 2;
    const int bk = tid >> 5;
    const int bn = (tid & 31) << 2;
    const int ty = (tid >> 4) << 3;
    const int tx = (tid & 15) << 3;

    for (int k0 = 0; k0 < K; k0 += 16) {
        float4 a0 = *(const float4*)(A + (size_t)ar      * lda + k0 + ak);
        float4 a1 = *(const float4*)(A + (size_t)(ar+64) * lda + k0 + ak);
        As[ak+0][ar] = a0.x; As[ak+1][ar] = a0.y; As[ak+2][ar] = a0.z; As[ak+3][ar] = a0.w;
        As[ak+0][ar+64] = a1.x; As[ak+1][ar+64] = a1.y; As[ak+2][ar+64] = a1.z; As[ak+3][ar+64] = a1.w;
        if (NT) {
            float4 b0 = *(const float4*)(B + (size_t)ar      * ldb + k0 + ak);
            float4 b1 = *(const float4*)(B + (size_t)(ar+64) * ldb + k0 + ak);
            Bs[ak+0][ar] = b0.x; Bs[ak+1][ar] = b0.y; Bs[ak+2][ar] = b0.z; Bs[ak+3][ar] = b0.w;
            Bs[ak+0][ar+64] = b1.x; Bs[ak+1][ar+64] = b1.y; Bs[ak+2][ar+64] = b1.z; Bs[ak+3][ar+64] = b1.w;
        } else {
            float4 b0 = *(const float4*)(B + (size_t)(k0+bk)   * ldb + bn);
            float4 b1 = *(const float4*)(B + (size_t)(k0+bk+8) * ldb + bn);
            *(float4*)&Bs[bk  ][bn] = b0;
            *(float4*)&Bs[bk+8][bn] = b1;
        }
        __syncthreads();
        #pragma unroll
        for (int kk = 0; kk < 16; kk++) {
            float a[8], b[8];
            *(float4*)&a[0] = *(const float4*)&As[kk][ty];
            *(float4*)&a[4] = *(const float4*)&As[kk][ty+4];
            *(float4*)&b[0] = *(const float4*)&Bs[kk][tx];
            *(float4*)&b[4] = *(const float4*)&Bs[kk][tx+4];
            #pragma unroll
            for (int i = 0; i < 8; i++)
                #pragma unroll
                for (int j = 0; j < 8; j++)
                    acc[i][j] = fmaf(a[i], b[j], acc[i][j]);
        }
        __syncthreads();
    }
}

__device__ __forceinline__ void store_tile(float* C, int ldc, float acc[8][8])
{
    const int tid = threadIdx.x;
    const int ty = (tid >> 4) << 3, tx = (tid & 15) << 3;
    #pragma unroll
    for (int i = 0; i < 8; i++) {
        *(float4*)(C + (size_t)(ty+i)*ldc + tx    ) = make_float4(acc[i][0],acc[i][1],acc[i][2],acc[i][3]);
        *(float4*)(C + (size_t)(ty+i)*ldc + tx + 4) = make_float4(acc[i][4],acc[i][5],acc[i][6],acc[i][7]);
    }
}

// ---------------- RoPE on Q -------------------------------------------------
__global__ void k_rope_q(const float* __restrict__ freqs)
{
    int idx = blockIdx.x*blockDim.x + threadIdx.x;
    int i = idx & 63;
    int h = (idx >> 6) & (NH-1);
    int m = idx >> 10;
    int s = m & (SEQ-1);
    float f = freqs[(size_t)s*64 + i];
    float sn, cs; sincosf(f, &sn, &cs);
    float* p = g_QKV + (size_t)m*QKVDIM + h*HD + 2*i;
    float2 v = *(float2*)p;
    float2 r;
    r.x = v.x*cs - v.y*sn;
    r.y = v.x*sn + v.y*cs;
    *(float2*)p = r;
}

// ---------------- RoPE on K + emit new_k ------------------------------------
__global__ void k_rope_k(const float* __restrict__ freqs, float* __restrict__ outk)
{
    int idx = blockIdx.x*blockDim.x + threadIdx.x;
    int i = idx & 63;
    int h = (idx >> 6) & (NKV-1);
    int m = idx >> 8;
    int s = m & (SEQ-1);
    float f = freqs[(size_t)s*64 + i];
    float sn, cs; sincosf(f, &sn, &cs);
    float* p = g_QKV + (size_t)m*QKVDIM + QDIM + h*HD + 2*i;
    float2 v = *(float2*)p;
    float2 r;
    r.x = v.x*cs - v.y*sn;
    r.y = v.x*sn + v.y*cs;
    *(float2*)p = r;
    *(float2*)(outk + (size_t)m*KVDIM + h*HD + 2*i) = r;
}

// ---------------- copy V -> new_v --------------------------------------------
__global__ void k_copy_v(float* __restrict__ outv)
{
    int idx = blockIdx.x*blockDim.x + threadIdx.x;   // MTOT*KVDIM/4 threads
    int m = idx >> 7, c = (idx & 127) * 4;
    float4 v = *(const float4*)(g_QKV + (size_t)m*QKVDIM + QDIM + KVDIM + c);
    *(float4*)(outv + (size_t)m*KVDIM + c) = v;
}

// ---------------- scores ----------------------------------------------------
__global__ void k_scores()
{
    const int qt = blockIdx.x, kt = blockIdx.y, bh = blockIdx.z;
    if (kt > qt) return;
    const int b = bh >> 4, h = bh & 15, kh = h >> 2;
    const float* A = g_QKV + (size_t)(b*SEQ + qt*128)*QKVDIM + h*HD;
    const float* B = g_QKV + (size_t)(b*SEQ + kt*128)*QKVDIM + QDIM + kh*HD;
    float acc[8][8];
    #pragma unroll
    for (int i = 0; i < 8; i++)
        #pragma unroll
        for (int j = 0; j < 8; j++) acc[i][j] = 0.f;
    gemm_mainloop<true>(A, QKVDIM, B, QKVDIM, HD, acc);

    float* C = g_S + (size_t)bh*SEQ*SEQ + (size_t)qt*128*SEQ + kt*128;
    const int tid = threadIdx.x;
    const int ty = (tid >> 4) << 3, tx = (tid & 15) << 3;
    const int qg0 = qt*128 + ty, kg0 = kt*128 + tx;
    #pragma unroll
    for (int i = 0; i < 8; i++)
        #pragma unroll
        for (int j = 0; j < 8; j++) {
            float v = acc[i][j] * ATTN_SCALE;
            if (kg0 + j > qg0 + i) v = NEGBIG;
            C[(size_t)(ty+i)*SEQ + tx + j] = v;
        }
}

// ---------------- row softmax ------------------------------------------------
__global__ void k_softmax()
{
    const int q = blockIdx.x, bh = blockIdx.y;
    float* row = g_S + (size_t)bh*SEQ*SEQ + (size_t)q*SEQ;
    const int len = q + 1;
    const int pad = ((q >> 7) + 1) << 7;
    const int tid = threadIdx.x;
    __shared__ float red[256];

    float m = -1e30f;
    for (int k = tid; k < len; k += 256) m = fmaxf(m, row[k]);
    red[tid] = m; __syncthreads();
    for (int off = 128; off; off >>= 1) {
        if (tid < off) red[tid] = fmaxf(red[tid], red[tid+off]);
        __syncthreads();
    }
    m = red[0]; __syncthreads();

    float s = 0.f;
    for (int k = tid; k < len; k += 256) {
        float e = __expf(row[k] - m);
        row[k] = e;
        s += e;
    }
    red[tid] = s; __syncthreads();
    for (int off = 128; off; off >>= 1) {
        if (tid < off) red[tid] += red[tid+off];
        __syncthreads();
    }
    const float inv = 1.0f / red[0];
    for (int k = tid; k < len; k += 256) row[k] *= inv;
    for (int k = len + tid; k < pad; k += 256) row[k] = 0.f;
}

// ---------------- PV ---------------------------------------------------------
__global__ void k_pv()
{
    const int qt = blockIdx.x, bh = blockIdx.y;
    const int b = bh >> 4, h = bh & 15, kh = h >> 2;
    const int K = (qt + 1) * 128;
    const float* A = g_S + (size_t)bh*SEQ*SEQ + (size_t)qt*128*SEQ;
    const float* B = g_QKV + (size_t)(b*SEQ)*QKVDIM + QDIM + KVDIM + kh*HD;
    float acc[8][8];
    #pragma unroll
    for (int i = 0; i < 8; i++)
        #pragma unroll
        for (int j = 0; j < 8; j++) acc[i][j] = 0.f;
    gemm_mainloop<false>(A, SEQ, B, QKVDIM, K, acc);
    store_tile(g_AO + (size_t)(b*SEQ + qt*128)*QDIM + h*HD, QDIM, acc);
}

// ---------------- launch -----------------------------------------------------
extern "C" void kernel_launch(void* const* d_in, const int* in_sizes, int n_in,
                              void* d_out, int out_size)
{
    const float* x     = (const float*)d_in[0];
    const float* wq    = (const float*)d_in[1];
    const float* wk    = (const float*)d_in[2];
    const float* wv    = (const float*)d_in[3];
    const float* wo    = (const float*)d_in[4];
    const float* freqs = (const float*)d_in[5];
    (void)in_sizes; (void)n_in; (void)out_size;

    float* out  = (float*)d_out;
    float* outk = out  + (size_t)MTOT*HIDDEN;
    float* outv = outk + (size_t)MTOT*KVDIM;

    float *QKVp, *AOp;
    __nv_bfloat16 *Xh, *Xl, *Wh, *Wl, *WOh, *WOl, *AOh, *AOl;
    cudaGetSymbolAddress((void**)&QKVp, g_QKV);
    cudaGetSymbolAddress((void**)&AOp,  g_AO);
    cudaGetSymbolAddress((void**)&Xh,   g_Xh);
    cudaGetSymbolAddress((void**)&Xl,   g_Xl);
    cudaGetSymbolAddress((void**)&Wh,   g_Wh);
    cudaGetSymbolAddress((void**)&Wl,   g_Wl);
    cudaGetSymbolAddress((void**)&WOh,  g_WOh);
    cudaGetSymbolAddress((void**)&WOl,  g_WOl);
    cudaGetSymbolAddress((void**)&AOh,  g_AOh);
    cudaGetSymbolAddress((void**)&AOl,  g_AOl);

    // 0. bf16 splits of inputs & weights
    k_split<<<(MTOT*HIDDEN/4 + 255)/256, 256>>>(x,  Xh, Xl, MTOT*HIDDEN/4);
    k_split<<<(QDIM*HIDDEN/4 + 255)/256, 256>>>(wq, Wh, Wl, QDIM*HIDDEN/4);
    k_split<<<(KVDIM*HIDDEN/4 + 255)/256, 256>>>(wk, Wh + (size_t)QDIM*HIDDEN,
                                                 Wl + (size_t)QDIM*HIDDEN, KVDIM*HIDDEN/4);
    k_split<<<(KVDIM*HIDDEN/4 + 255)/256, 256>>>(wv, Wh + (size_t)(QDIM+KVDIM)*HIDDEN,
                                                 Wl + (size_t)(QDIM+KVDIM)*HIDDEN, KVDIM*HIDDEN/4);
    k_split<<<(HIDDEN*QDIM/4 + 255)/256, 256>>>(wo, WOh, WOl, HIDDEN*QDIM/4);

    // 1. fused QKV projection on tensor cores (HMMA): [4096,3072] = X @ Wqkv^T
    mma_gemm<<<dim3(QKVDIM/128, MTOT/128), 256>>>(Xh, Xl, Wh, Wl, QKVp, QKVDIM, HIDDEN);

    // 2. rope + kv-cache outputs
    k_rope_q<<<(MTOT*NH *64)/256, 256>>>(freqs);
    k_rope_k<<<(MTOT*NKV*64)/256, 256>>>(freqs, outk);
    k_copy_v<<<(MTOT*KVDIM/4)/256, 256>>>(outv);

    // 3-5. attention (SIMT fp32)
    k_scores <<<dim3(SEQ/128, SEQ/128, BATCH*NH), 256>>>();
    k_softmax<<<dim3(SEQ, BATCH*NH), 256>>>();
    k_pv     <<<dim3(SEQ/128, BATCH*NH), 256>>>();

    // 6. output projection on tensor cores (HMMA)
    k_split<<<(MTOT*QDIM/4 + 255)/256, 256>>>(AOp, AOh, AOl, MTOT*QDIM/4);
    mma_gemm<<<dim3(HIDDEN/128, MTOT/128), 256>>>(AOh, AOl, WOh, WOl, out, HIDDEN, QDIM);
}

// round 5
// speedup vs baseline: 2.9559x; 1.7900x over previous
#include <cuda_runtime.h>
#include <cuda_bf16.h>
#include <math.h>
#include <stdint.h>

#define BATCH   2
#define SEQ     2048
#define HIDDEN  2048
#define NH      16
#define NKV     4
#define HD      128
#define MTOT    (BATCH*SEQ)      // 4096
#define QDIM    (NH*HD)          // 2048
#define KVDIM   (NKV*HD)         // 512
#define QKVDIM  (QDIM+2*KVDIM)   // 3072
#define ATTN_SCALE 0.08838834764831845f
#define CS (ATTN_SCALE * 1.4426950408889634f)   // scale * log2(e)

// ---------------- scratch (device globals; no allocation allowed) ----------
__device__ float g_QKV[(size_t)MTOT*QKVDIM];            // 50 MB  (Q | K | V per row)
__device__ __nv_bfloat16 g_Xh[(size_t)MTOT*HIDDEN];
__device__ __nv_bfloat16 g_Xl[(size_t)MTOT*HIDDEN];
__device__ __nv_bfloat16 g_Wh[(size_t)QKVDIM*HIDDEN];
__device__ __nv_bfloat16 g_Wl[(size_t)QKVDIM*HIDDEN];
__device__ __nv_bfloat16 g_WOh[(size_t)HIDDEN*QDIM];
__device__ __nv_bfloat16 g_WOl[(size_t)HIDDEN*QDIM];
__device__ __nv_bfloat16 g_QKVh[(size_t)MTOT*QKVDIM];   // 25 MB
__device__ __nv_bfloat16 g_QKVl[(size_t)MTOT*QKVDIM];
__device__ __nv_bfloat16 g_AOh[(size_t)MTOT*QDIM];
__device__ __nv_bfloat16 g_AOl[(size_t)MTOT*QDIM];

// ================= HMMA helpers ============================================
__device__ __forceinline__ void ldsm_x4(uint32_t* r, uint32_t addr) {
    asm volatile("ldmatrix.sync.aligned.m8n8.x4.shared.b16 {%0,%1,%2,%3}, [%4];"
                 : "=r"(r[0]), "=r"(r[1]), "=r"(r[2]), "=r"(r[3]) : "r"(addr));
}
__device__ __forceinline__ void ldsm_x2(uint32_t* r, uint32_t addr) {
    asm volatile("ldmatrix.sync.aligned.m8n8.x2.shared.b16 {%0,%1}, [%2];"
                 : "=r"(r[0]), "=r"(r[1]) : "r"(addr));
}
__device__ __forceinline__ void ldsm_x4_t(uint32_t* r, uint32_t addr) {
    asm volatile("ldmatrix.sync.aligned.m8n8.x4.trans.shared.b16 {%0,%1,%2,%3}, [%4];"
                 : "=r"(r[0]), "=r"(r[1]), "=r"(r[2]), "=r"(r[3]) : "r"(addr));
}
__device__ __forceinline__ void mma16816(float* d, const uint32_t* a, const uint32_t* b) {
    asm volatile("mma.sync.aligned.m16n8k16.row.col.f32.bf16.bf16.f32 "
                 "{%0,%1,%2,%3},{%4,%5,%6,%7},{%8,%9},{%0,%1,%2,%3};"
                 : "+f"(d[0]), "+f"(d[1]), "+f"(d[2]), "+f"(d[3])
                 : "r"(a[0]), "r"(a[1]), "r"(a[2]), "r"(a[3]), "r"(b[0]), "r"(b[1]));
}
__device__ __forceinline__ uint32_t smem_u32(const void* p) {
    return (uint32_t)__cvta_generic_to_shared(p);
}
__device__ __forceinline__ float ex2f(float x) {
    float r; asm("ex2.approx.ftz.f32 %0, %1;" : "=f"(r) : "f"(x)); return r;
}
__device__ __forceinline__ uint32_t packbf(float lo, float hi) {  // {lo half, hi half}
    uint32_t d; asm("cvt.rn.bf16x2.f32 %0, %1, %2;" : "=r"(d) : "f"(hi), "f"(lo)); return d;
}
__device__ __forceinline__ float bf16rt(float x) {
    return __bfloat162float(__float2bfloat16(x));
}

// ============ HMMA GEMM: C[M,N](fp32) = (Ah+Al)[M,K] @ (Bh+Bl)[N,K]^T =======
#define BK   32
#define SLD  40

__global__ void __launch_bounds__(256, 2) mma_gemm(
    const __nv_bfloat16* __restrict__ Ah, const __nv_bfloat16* __restrict__ Al,
    const __nv_bfloat16* __restrict__ Bh, const __nv_bfloat16* __restrict__ Bl,
    float* __restrict__ C, int ldc, int K)
{
    __shared__ __nv_bfloat16 sAh[128][SLD];
    __shared__ __nv_bfloat16 sAl[128][SLD];
    __shared__ __nv_bfloat16 sBh[128][SLD];
    __shared__ __nv_bfloat16 sBl[128][SLD];

    const int tid  = threadIdx.x;
    const int lane = tid & 31;
    const int wid  = tid >> 5;
    const int wr   = wid >> 2;
    const int wc   = wid & 3;

    float acc[4][4][4];
    #pragma unroll
    for (int m = 0; m < 4; m++)
        #pragma unroll
        for (int n = 0; n < 4; n++)
            #pragma unroll
            for (int i = 0; i < 4; i++) acc[m][n][i] = 0.f;

    const size_t arow0 = (size_t)blockIdx.y * 128;
    const size_t brow0 = (size_t)blockIdx.x * 128;

    const int a_r = lane & 15, a_c = ((lane >> 4) & 1) * 8;
    const int b_r = lane & 7,  b_c = ((lane >> 3) & 1) * 8;

    for (int k0 = 0; k0 < K; k0 += BK) {
        #pragma unroll
        for (int t = 0; t < 2; t++) {
            int idx = tid + t * 256;
            int r = idx >> 2, c = idx & 3;
            *(uint4*)&sAh[r][c * 8] = *(const uint4*)(Ah + (arow0 + r) * K + k0 + c * 8);
            *(uint4*)&sAl[r][c * 8] = *(const uint4*)(Al + (arow0 + r) * K + k0 + c * 8);
            *(uint4*)&sBh[r][c * 8] = *(const uint4*)(Bh + (brow0 + r) * K + k0 + c * 8);
            *(uint4*)&sBl[r][c * 8] = *(const uint4*)(Bl + (brow0 + r) * K + k0 + c * 8);
        }
        __syncthreads();

        #pragma unroll
        for (int kk = 0; kk < BK; kk += 16) {
            uint32_t bh[4][2], bl[4][2];
            #pragma unroll
            for (int n = 0; n < 4; n++) {
                int row = wc * 32 + n * 8 + b_r;
                ldsm_x2(bh[n], smem_u32(&sBh[row][kk + b_c]));
                ldsm_x2(bl[n], smem_u32(&sBl[row][kk + b_c]));
            }
            #pragma unroll
            for (int m = 0; m < 4; m++) {
                uint32_t ah[4], al[4];
                int row = wr * 64 + m * 16 + a_r;
                ldsm_x4(ah, smem_u32(&sAh[row][kk + a_c]));
                ldsm_x4(al, smem_u32(&sAl[row][kk + a_c]));
                #pragma unroll
                for (int n = 0; n < 4; n++) {
                    mma16816(acc[m][n], ah, bh[n]);
                    mma16816(acc[m][n], ah, bl[n]);
                    mma16816(acc[m][n], al, bh[n]);
                }
            }
        }
        __syncthreads();
    }

    const int r0 = lane >> 2, cbase = (lane & 3) * 2;
    #pragma unroll
    for (int m = 0; m < 4; m++) {
        size_t grow = arow0 + wr * 64 + m * 16 + r0;
        #pragma unroll
        for (int n = 0; n < 4; n++) {
            size_t gcol = brow0 + wc * 32 + n * 8 + cbase;
            *(float2*)(C + grow * ldc + gcol)       = make_float2(acc[m][n][0], acc[m][n][1]);
            *(float2*)(C + (grow + 8) * ldc + gcol) = make_float2(acc[m][n][2], acc[m][n][3]);
        }
    }
}

// ---------------- fp32 -> bf16 hi/lo split ----------------------------------
__global__ void k_split(const float* __restrict__ src, __nv_bfloat16* __restrict__ hi,
                        __nv_bfloat16* __restrict__ lo, int n4)
{
    int i = blockIdx.x * blockDim.x + threadIdx.x;
    if (i >= n4) return;
    float4 v = ((const float4*)src)[i];
    __nv_bfloat16 h0 = __float2bfloat16(v.x), h1 = __float2bfloat16(v.y);
    __nv_bfloat16 h2 = __float2bfloat16(v.z), h3 = __float2bfloat16(v.w);
    __nv_bfloat16 l0 = __float2bfloat16(v.x - __bfloat162float(h0));
    __nv_bfloat16 l1 = __float2bfloat16(v.y - __bfloat162float(h1));
    __nv_bfloat16 l2 = __float2bfloat16(v.z - __bfloat162float(h2));
    __nv_bfloat16 l3 = __float2bfloat16(v.w - __bfloat162float(h3));
    ushort4 hv = make_ushort4(*(unsigned short*)&h0, *(unsigned short*)&h1,
                              *(unsigned short*)&h2, *(unsigned short*)&h3);
    ushort4 lv = make_ushort4(*(unsigned short*)&l0, *(unsigned short*)&l1,
                              *(unsigned short*)&l2, *(unsigned short*)&l3);
    ((ushort4*)hi)[i] = hv;
    ((ushort4*)lo)[i] = lv;
}

// ---------------- RoPE on Q -------------------------------------------------
__global__ void k_rope_q(const float* __restrict__ freqs)
{
    int idx = blockIdx.x*blockDim.x + threadIdx.x;
    int i = idx & 63;
    int h = (idx >> 6) & (NH-1);
    int m = idx >> 10;
    int s = m & (SEQ-1);
    float f = freqs[(size_t)s*64 + i];
    float sn, cs; sincosf(f, &sn, &cs);
    float* p = g_QKV + (size_t)m*QKVDIM + h*HD + 2*i;
    float2 v = *(float2*)p;
    float2 r;
    r.x = v.x*cs - v.y*sn;
    r.y = v.x*sn + v.y*cs;
    *(float2*)p = r;
}

// ---------------- RoPE on K + emit new_k ------------------------------------
__global__ void k_rope_k(const float* __restrict__ freqs, float* __restrict__ outk)
{
    int idx = blockIdx.x*blockDim.x + threadIdx.x;
    int i = idx & 63;
    int h = (idx >> 6) & (NKV-1);
    int m = idx >> 8;
    int s = m & (SEQ-1);
    float f = freqs[(size_t)s*64 + i];
    float sn, cs; sincosf(f, &sn, &cs);
    float* p = g_QKV + (size_t)m*QKVDIM + QDIM + h*HD + 2*i;
    float2 v = *(float2*)p;
    float2 r;
    r.x = v.x*cs - v.y*sn;
    r.y = v.x*sn + v.y*cs;
    *(float2*)p = r;
    *(float2*)(outk + (size_t)m*KVDIM + h*HD + 2*i) = r;
}

// ---------------- copy V -> new_v --------------------------------------------
__global__ void k_copy_v(float* __restrict__ outv)
{
    int idx = blockIdx.x*blockDim.x + threadIdx.x;
    int m = idx >> 7, c = (idx & 127) * 4;
    float4 v = *(const float4*)(g_QKV + (size_t)m*QKVDIM + QDIM + KVDIM + c);
    *(float4*)(outv + (size_t)m*KVDIM + c) = v;
}

// ============ fused flash attention (HMMA, bf16 hi/lo split) =================
// CTA: 128 q rows x one (b,h). 8 warps, 16 rows each, full 128 cols per warp.
#define TILE_B 34816     // 128 * 136 * 2 bytes
#define FLASH_SMEM (6 * TILE_B)

__global__ void __launch_bounds__(256, 1) k_flash(
    const __nv_bfloat16* __restrict__ QKVh, const __nv_bfloat16* __restrict__ QKVl,
    __nv_bfloat16* __restrict__ AOh, __nv_bfloat16* __restrict__ AOl)
{
    extern __shared__ char smraw[];
    typedef __nv_bfloat16 (*tile_t)[136];
    tile_t sQh = (tile_t)(smraw);
    tile_t sQl = (tile_t)(smraw + 1*TILE_B);
    tile_t sKh = (tile_t)(smraw + 2*TILE_B);
    tile_t sKl = (tile_t)(smraw + 3*TILE_B);
    tile_t sVh = (tile_t)(smraw + 4*TILE_B);
    tile_t sVl = (tile_t)(smraw + 5*TILE_B);

    const int qt = (int)gridDim.x - 1 - (int)blockIdx.x;   // heavy tiles first
    const int bh = blockIdx.y;
    const int b = bh >> 4, h = bh & 15, kh = h >> 2;
    const int tid = threadIdx.x, lane = tid & 31, wid = tid >> 5;

    // load Q tile once
    const size_t qbase = ((size_t)(b*SEQ + qt*128))*QKVDIM + h*HD;
    for (int i = tid; i < 2048; i += 256) {
        int r = i >> 4, c = (i & 15) * 8;
        *(uint4*)&sQh[r][c] = *(const uint4*)(QKVh + qbase + (size_t)r*QKVDIM + c);
        *(uint4*)&sQl[r][c] = *(const uint4*)(QKVl + qbase + (size_t)r*QKVDIM + c);
    }

    float oacc[16][4];
    #pragma unroll
    for (int n = 0; n < 16; n++)
        #pragma unroll
        for (int i = 0; i < 4; i++) oacc[n][i] = 0.f;
    float mi0 = -1e30f, mi1 = -1e30f, li0 = 0.f, li1 = 0.f;

    // ldsm per-thread offsets
    const int q_r  = wid*16 + (lane & 15);
    const int q_c  = (lane >> 4) * 8;
    const int k_ro = ((lane >> 4) & 1) * 8 + (lane & 7);   // K b-frags (non-trans)
    const int k_co = ((lane >> 3) & 1) * 8;
    const int v_ro = ((lane >> 3) & 1) * 8 + (lane & 7);   // V b-frags (trans)
    const int v_co = ((lane >> 4) & 1) * 8;
    const int r_lo = lane >> 2;            // local row within 16-row slab
    const int c_lo = (lane & 3) * 2;       // local col pair base

    for (int kt = 0; kt <= qt; kt++) {
        __syncthreads();   // previous iter's V reads done
        const size_t kbase = ((size_t)(b*SEQ + kt*128))*QKVDIM + QDIM + kh*HD;
        const size_t vbase = kbase + KVDIM;
        for (int i = tid; i < 2048; i += 256) {
            int r = i >> 4, c = (i & 15) * 8;
            *(uint4*)&sKh[r][c] = *(const uint4*)(QKVh + kbase + (size_t)r*QKVDIM + c);
            *(uint4*)&sKl[r][c] = *(const uint4*)(QKVl + kbase + (size_t)r*QKVDIM + c);
            *(uint4*)&sVh[r][c] = *(const uint4*)(QKVh + vbase + (size_t)r*QKVDIM + c);
            *(uint4*)&sVl[r][c] = *(const uint4*)(QKVl + vbase + (size_t)r*QKVDIM + c);
        }
        __syncthreads();

        // ---- S = Q K^T (3-pass split) ----
        float sacc[16][4];
        #pragma unroll
        for (int n = 0; n < 16; n++)
            #pragma unroll
            for (int i = 0; i < 4; i++) sacc[n][i] = 0.f;

        #pragma unroll
        for (int kk = 0; kk < 8; kk++) {
            uint32_t ah[4], al[4];
            ldsm_x4(ah, smem_u32(&sQh[q_r][kk*16 + q_c]));
            ldsm_x4(al, smem_u32(&sQl[q_r][kk*16 + q_c]));
            #pragma unroll
            for (int j2 = 0; j2 < 8; j2++) {
                uint32_t kb[4], klb[4];
                ldsm_x4(kb,  smem_u32(&sKh[16*j2 + k_ro][kk*16 + k_co]));
                ldsm_x4(klb, smem_u32(&sKl[16*j2 + k_ro][kk*16 + k_co]));
                mma16816(sacc[2*j2],   ah, kb);
                mma16816(sacc[2*j2],   ah, klb);
                mma16816(sacc[2*j2],   al, kb);
                mma16816(sacc[2*j2+1], ah, kb + 2);
                mma16816(sacc[2*j2+1], ah, klb + 2);
                mma16816(sacc[2*j2+1], al, kb + 2);
            }
        }

        // ---- scale (+ causal mask on diag tile), row max ----
        const bool diag = (kt == qt);
        float mx0 = -1e30f, mx1 = -1e30f;
        #pragma unroll
        for (int n = 0; n < 16; n++) {
            float e0 = sacc[n][0]*CS, e1 = sacc[n][1]*CS;
            float e2 = sacc[n][2]*CS, e3 = sacc[n][3]*CS;
            if (diag) {
                int c0 = n*8 + c_lo;
                int r0 = wid*16 + r_lo;
                if (c0     > r0)     e0 = -1e30f;
                if (c0 + 1 > r0)     e1 = -1e30f;
                if (c0     > r0 + 8) e2 = -1e30f;
                if (c0 + 1 > r0 + 8) e3 = -1e30f;
            }
            sacc[n][0] = e0; sacc[n][1] = e1; sacc[n][2] = e2; sacc[n][3] = e3;
            mx0 = fmaxf(mx0, fmaxf(e0, e1));
            mx1 = fmaxf(mx1, fmaxf(e2, e3));
        }
        mx0 = fmaxf(mx0, __shfl_xor_sync(0xffffffffu, mx0, 1));
        mx0 = fmaxf(mx0, __shfl_xor_sync(0xffffffffu, mx0, 2));
        mx1 = fmaxf(mx1, __shfl_xor_sync(0xffffffffu, mx1, 1));
        mx1 = fmaxf(mx1, __shfl_xor_sync(0xffffffffu, mx1, 2));

        float mn0 = fmaxf(mi0, mx0), mn1 = fmaxf(mi1, mx1);
        float al0 = ex2f(mi0 - mn0), al1 = ex2f(mi1 - mn1);
        mi0 = mn0; mi1 = mn1;

        // ---- P = exp2(e - m), row sums ----
        float s0 = 0.f, s1 = 0.f;
        #pragma unroll
        for (int n = 0; n < 16; n++) {
            float p0 = ex2f(sacc[n][0] - mn0), p1 = ex2f(sacc[n][1] - mn0);
            float p2 = ex2f(sacc[n][2] - mn1), p3 = ex2f(sacc[n][3] - mn1);
            sacc[n][0] = p0; sacc[n][1] = p1; sacc[n][2] = p2; sacc[n][3] = p3;
            s0 += p0 + p1; s1 += p2 + p3;
        }
        s0 += __shfl_xor_sync(0xffffffffu, s0, 1);
        s0 += __shfl_xor_sync(0xffffffffu, s0, 2);
        s1 += __shfl_xor_sync(0xffffffffu, s1, 1);
        s1 += __shfl_xor_sync(0xffffffffu, s1, 2);
        li0 = li0 * al0 + s0;
        li1 = li1 * al1 + s1;

        #pragma unroll
        for (int n = 0; n < 16; n++) {
            oacc[n][0] *= al0; oacc[n][1] *= al0;
            oacc[n][2] *= al1; oacc[n][3] *= al1;
        }

        // ---- O += P V (3-pass split) ----
        #pragma unroll
        for (int kk2 = 0; kk2 < 8; kk2++) {
            // P a-frags from sacc (hi + lo bf16)
            float p00 = sacc[2*kk2][0],   p01 = sacc[2*kk2][1];
            float p02 = sacc[2*kk2][2],   p03 = sacc[2*kk2][3];
            float p10 = sacc[2*kk2+1][0], p11 = sacc[2*kk2+1][1];
            float p12 = sacc[2*kk2+1][2], p13 = sacc[2*kk2+1][3];
            uint32_t pah[4], pal[4];
            pah[0] = packbf(p00, p01); pah[1] = packbf(p02, p03);
            pah[2] = packbf(p10, p11); pah[3] = packbf(p12, p13);
            pal[0] = packbf(p00 - bf16rt(p00), p01 - bf16rt(p01));
            pal[1] = packbf(p02 - bf16rt(p02), p03 - bf16rt(p03));
            pal[2] = packbf(p10 - bf16rt(p10), p11 - bf16rt(p11));
            pal[3] = packbf(p12 - bf16rt(p12), p13 - bf16rt(p13));

            #pragma unroll
            for (int j = 0; j < 8; j++) {
                uint32_t vb[4], vlb[4];
                ldsm_x4_t(vb,  smem_u32(&sVh[kk2*16 + v_ro][16*j + v_co]));
                ldsm_x4_t(vlb, smem_u32(&sVl[kk2*16 + v_ro][16*j + v_co]));
                mma16816(oacc[2*j],   pah, vb);
                mma16816(oacc[2*j],   pah, vlb);
                mma16816(oacc[2*j],   pal, vb);
                mma16816(oacc[2*j+1], pah, vb + 2);
                mma16816(oacc[2*j+1], pah, vlb + 2);
                mma16816(oacc[2*j+1], pal, vb + 2);
            }
        }
    }

    // ---- epilogue: O /= l, write bf16 hi/lo directly ----
    float inv0 = 1.f / li0, inv1 = 1.f / li1;
    size_t row0 = (size_t)(b*SEQ + qt*128 + wid*16 + r_lo);
    size_t colb = (size_t)h*HD + c_lo;
    #pragma unroll
    for (int n = 0; n < 16; n++) {
        float v0 = oacc[n][0]*inv0, v1 = oacc[n][1]*inv0;
        float v2 = oacc[n][2]*inv1, v3 = oacc[n][3]*inv1;
        size_t o0 = row0*QDIM + colb + n*8;
        size_t o1 = (row0+8)*QDIM + colb + n*8;
        *(uint32_t*)&AOh[o0] = packbf(bf16rt(v0), bf16rt(v1));
        *(uint32_t*)&AOl[o0] = packbf(v0 - bf16rt(v0), v1 - bf16rt(v1));
        *(uint32_t*)&AOh[o1] = packbf(bf16rt(v2), bf16rt(v3));
        *(uint32_t*)&AOl[o1] = packbf(v2 - bf16rt(v2), v3 - bf16rt(v3));
    }
}

// ---------------- launch -----------------------------------------------------
extern "C" void kernel_launch(void* const* d_in, const int* in_sizes, int n_in,
                              void* d_out, int out_size)
{
    const float* x     = (const float*)d_in[0];
    const float* wq    = (const float*)d_in[1];
    const float* wk    = (const float*)d_in[2];
    const float* wv    = (const float*)d_in[3];
    const float* wo    = (const float*)d_in[4];
    const float* freqs = (const float*)d_in[5];
    (void)in_sizes; (void)n_in; (void)out_size;

    float* out  = (float*)d_out;
    float* outk = out  + (size_t)MTOT*HIDDEN;
    float* outv = outk + (size_t)MTOT*KVDIM;

    float *QKVp;
    __nv_bfloat16 *Xh, *Xl, *Wh, *Wl, *WOh, *WOl, *AOh, *AOl, *QKVh, *QKVl;
    cudaGetSymbolAddress((void**)&QKVp, g_QKV);
    cudaGetSymbolAddress((void**)&Xh,   g_Xh);
    cudaGetSymbolAddress((void**)&Xl,   g_Xl);
    cudaGetSymbolAddress((void**)&Wh,   g_Wh);
    cudaGetSymbolAddress((void**)&Wl,   g_Wl);
    cudaGetSymbolAddress((void**)&WOh,  g_WOh);
    cudaGetSymbolAddress((void**)&WOl,  g_WOl);
    cudaGetSymbolAddress((void**)&AOh,  g_AOh);
    cudaGetSymbolAddress((void**)&AOl,  g_AOl);
    cudaGetSymbolAddress((void**)&QKVh, g_QKVh);
    cudaGetSymbolAddress((void**)&QKVl, g_QKVl);

    cudaFuncSetAttribute(k_flash, cudaFuncAttributeMaxDynamicSharedMemorySize, FLASH_SMEM);

    // 0. bf16 splits of inputs & weights
    k_split<<<(MTOT*HIDDEN/4 + 255)/256, 256>>>(x,  Xh, Xl, MTOT*HIDDEN/4);
    k_split<<<(QDIM*HIDDEN/4 + 255)/256, 256>>>(wq, Wh, Wl, QDIM*HIDDEN/4);
    k_split<<<(KVDIM*HIDDEN/4 + 255)/256, 256>>>(wk, Wh + (size_t)QDIM*HIDDEN,
                                                 Wl + (size_t)QDIM*HIDDEN, KVDIM*HIDDEN/4);
    k_split<<<(KVDIM*HIDDEN/4 + 255)/256, 256>>>(wv, Wh + (size_t)(QDIM+KVDIM)*HIDDEN,
                                                 Wl + (size_t)(QDIM+KVDIM)*HIDDEN, KVDIM*HIDDEN/4);
    k_split<<<(HIDDEN*QDIM/4 + 255)/256, 256>>>(wo, WOh, WOl, HIDDEN*QDIM/4);

    // 1. fused QKV projection (HMMA)
    mma_gemm<<<dim3(QKVDIM/128, MTOT/128), 256>>>(Xh, Xl, Wh, Wl, QKVp, QKVDIM, HIDDEN);

    // 2. rope + kv-cache outputs
    k_rope_q<<<(MTOT*NH *64)/256, 256>>>(freqs);
    k_rope_k<<<(MTOT*NKV*64)/256, 256>>>(freqs, outk);
    k_copy_v<<<(MTOT*KVDIM/4)/256, 256>>>(outv);

    // 3. bf16 split of rope'd QKV
    k_split<<<(MTOT*QKVDIM/4 + 255)/256, 256>>>(QKVp, QKVh, QKVl, MTOT*QKVDIM/4);

    // 4. fused flash attention -> AOh/AOl (bf16 hi/lo)
    k_flash<<<dim3(SEQ/128, BATCH*NH), 256, FLASH_SMEM>>>(QKVh, QKVl, AOh, AOl);

    // 5. output projection (HMMA)
    mma_gemm<<<dim3(HIDDEN/128, MTOT/128), 256>>>(AOh, AOl, WOh, WOl, out, HIDDEN, QDIM);
}

// round 8
// speedup vs baseline: 3.1800x; 1.0758x over previous
#include <cuda_runtime.h>
#include <cuda_bf16.h>
#include <math.h>
#include <stdint.h>

#define BATCH   2
#define SEQ     2048
#define HIDDEN  2048
#define NH      16
#define NKV     4
#define HD      128
#define MTOT    (BATCH*SEQ)      // 4096
#define QDIM    (NH*HD)          // 2048
#define KVDIM   (NKV*HD)         // 512
#define QKVDIM  (QDIM+2*KVDIM)   // 3072
#define ATTN_SCALE 0.08838834764831845f
#define CS (ATTN_SCALE * 1.4426950408889634f)   // scale * log2(e)

// ---------------- scratch (device globals; no allocation allowed) ----------
__device__ float g_QKV[(size_t)MTOT*QKVDIM];            // 50 MB  (Q | K | V per row)
__device__ __nv_bfloat16 g_Xh[(size_t)MTOT*HIDDEN];
__device__ __nv_bfloat16 g_Xl[(size_t)MTOT*HIDDEN];
__device__ __nv_bfloat16 g_Wh[(size_t)QKVDIM*HIDDEN];
__device__ __nv_bfloat16 g_Wl[(size_t)QKVDIM*HIDDEN];
__device__ __nv_bfloat16 g_WOh[(size_t)HIDDEN*QDIM];
__device__ __nv_bfloat16 g_WOl[(size_t)HIDDEN*QDIM];
__device__ __nv_bfloat16 g_QKVh[(size_t)MTOT*QKVDIM];   // 25 MB
__device__ __nv_bfloat16 g_QKVl[(size_t)MTOT*QKVDIM];
__device__ __nv_bfloat16 g_AOh[(size_t)MTOT*QDIM];
__device__ __nv_bfloat16 g_AOl[(size_t)MTOT*QDIM];

// ================= helpers ==================================================
__device__ __forceinline__ void ldsm_x4(uint32_t* r, uint32_t addr) {
    asm volatile("ldmatrix.sync.aligned.m8n8.x4.shared.b16 {%0,%1,%2,%3}, [%4];"
                 : "=r"(r[0]), "=r"(r[1]), "=r"(r[2]), "=r"(r[3]) : "r"(addr));
}
__device__ __forceinline__ void ldsm_x2(uint32_t* r, uint32_t addr) {
    asm volatile("ldmatrix.sync.aligned.m8n8.x2.shared.b16 {%0,%1}, [%2];"
                 : "=r"(r[0]), "=r"(r[1]) : "r"(addr));
}
__device__ __forceinline__ void ldsm_x4_t(uint32_t* r, uint32_t addr) {
    asm volatile("ldmatrix.sync.aligned.m8n8.x4.trans.shared.b16 {%0,%1,%2,%3}, [%4];"
                 : "=r"(r[0]), "=r"(r[1]), "=r"(r[2]), "=r"(r[3]) : "r"(addr));
}
__device__ __forceinline__ void mma16816(float* d, const uint32_t* a, const uint32_t* b) {
    asm volatile("mma.sync.aligned.m16n8k16.row.col.f32.bf16.bf16.f32 "
                 "{%0,%1,%2,%3},{%4,%5,%6,%7},{%8,%9},{%0,%1,%2,%3};"
                 : "+f"(d[0]), "+f"(d[1]), "+f"(d[2]), "+f"(d[3])
                 : "r"(a[0]), "r"(a[1]), "r"(a[2]), "r"(a[3]), "r"(b[0]), "r"(b[1]));
}
__device__ __forceinline__ uint32_t smem_u32(const void* p) {
    return (uint32_t)__cvta_generic_to_shared(p);
}
__device__ __forceinline__ float ex2f(float x) {
    float r; asm("ex2.approx.ftz.f32 %0, %1;" : "=f"(r) : "f"(x)); return r;
}
__device__ __forceinline__ uint32_t packbf(float lo, float hi) {  // lo -> low half
    uint32_t d; asm("cvt.rn.bf16x2.f32 %0, %1, %2;" : "=r"(d) : "f"(hi), "f"(lo)); return d;
}
__device__ __forceinline__ float bf16rt(float x) {
    return __bfloat162float(__float2bfloat16(x));
}
#define CP_ASYNC16(sa, gp) \
    asm volatile("cp.async.cg.shared.global [%0], [%1], 16;" :: "r"(sa), "l"(gp))
#define CP_COMMIT() asm volatile("cp.async.commit_group;" ::: "memory")
#define CP_WAIT0()  asm volatile("cp.async.wait_group 0;" ::: "memory")
#define CP_WAIT1()  asm volatile("cp.async.wait_group 1;" ::: "memory")

// ============ HMMA GEMM, 2-stage cp.async pipeline ==========================
#define BK    32
#define SLD   40
#define TILE_HALVES  (128*SLD)
#define STAGE_HALVES (4*TILE_HALVES)
#define GEMM_SMEM    (2*STAGE_HALVES*2)   // 81920 bytes

__global__ void __launch_bounds__(256, 2) mma_gemm(
    const __nv_bfloat16* __restrict__ Ah, const __nv_bfloat16* __restrict__ Al,
    const __nv_bfloat16* __restrict__ Bh, const __nv_bfloat16* __restrict__ Bl,
    float* __restrict__ C, int ldc, int K)
{
    extern __shared__ __nv_bfloat16 sm[];
    const int tid  = threadIdx.x;
    const int lane = tid & 31;
    const int wid  = tid >> 5;
    const int wr   = wid >> 2;
    const int wc   = wid & 3;

    float acc[4][4][4];
    #pragma unroll
    for (int m = 0; m < 4; m++)
        #pragma unroll
        for (int n = 0; n < 4; n++)
            #pragma unroll
            for (int i = 0; i < 4; i++) acc[m][n][i] = 0.f;

    const size_t arow0 = (size_t)blockIdx.y * 128;
    const size_t brow0 = (size_t)blockIdx.x * 128;

    const int a_r = lane & 15, a_c = ((lane >> 4) & 1) * 8;
    const int b_r = lane & 7,  b_c = ((lane >> 3) & 1) * 8;
    const int nk = K / BK;

    auto issue_stage = [&](int sel, int k0) {
        __nv_bfloat16* base = sm + sel * STAGE_HALVES;
        const __nv_bfloat16* srcs[4] = { Ah + arow0*K + k0, Al + arow0*K + k0,
                                         Bh + brow0*K + k0, Bl + brow0*K + k0 };
        #pragma unroll
        for (int t = 0; t < 4; t++) {
            __nv_bfloat16* dst = base + t * TILE_HALVES;
            #pragma unroll
            for (int u = 0; u < 2; u++) {
                int idx = tid + u * 256;
                int r = idx >> 2, c = (idx & 3) * 8;
                CP_ASYNC16(smem_u32(dst + r*SLD + c), srcs[t] + (size_t)r*K + c);
            }
        }
        CP_COMMIT();
    };

    issue_stage(0, 0);
    for (int i = 0; i < nk; i++) {
        if (i + 1 < nk) { issue_stage((i + 1) & 1, (i + 1) * BK); CP_WAIT1(); }
        else            { CP_WAIT0(); }
        __syncthreads();

        __nv_bfloat16* base = sm + (i & 1) * STAGE_HALVES;
        __nv_bfloat16* bAh = base;
        __nv_bfloat16* bAl = base + 1*TILE_HALVES;
        __nv_bfloat16* bBh = base + 2*TILE_HALVES;
        __nv_bfloat16* bBl = base + 3*TILE_HALVES;

        #pragma unroll
        for (int kk = 0; kk < BK; kk += 16) {
            uint32_t bhf[4][2], blf[4][2];
            #pragma unroll
            for (int n = 0; n < 4; n++) {
                int row = wc * 32 + n * 8 + b_r;
                ldsm_x2(bhf[n], smem_u32(bBh + row*SLD + kk + b_c));
                ldsm_x2(blf[n], smem_u32(bBl + row*SLD + kk + b_c));
            }
            #pragma unroll
            for (int m = 0; m < 4; m++) {
                uint32_t ah[4], al[4];
                int row = wr * 64 + m * 16 + a_r;
                ldsm_x4(ah, smem_u32(bAh + row*SLD + kk + a_c));
                ldsm_x4(al, smem_u32(bAl + row*SLD + kk + a_c));
                #pragma unroll
                for (int n = 0; n < 4; n++) {
                    mma16816(acc[m][n], ah, bhf[n]);
                    mma16816(acc[m][n], ah, blf[n]);
                    mma16816(acc[m][n], al, bhf[n]);
                }
            }
        }
        __syncthreads();
    }

    const int r0 = lane >> 2, cbase = (lane & 3) * 2;
    #pragma unroll
    for (int m = 0; m < 4; m++) {
        size_t grow = arow0 + wr * 64 + m * 16 + r0;
        #pragma unroll
        for (int n = 0; n < 4; n++) {
            size_t gcol = brow0 + wc * 32 + n * 8 + cbase;
            *(float2*)(C + grow * ldc + gcol)       = make_float2(acc[m][n][0], acc[m][n][1]);
            *(float2*)(C + (grow + 8) * ldc + gcol) = make_float2(acc[m][n][2], acc[m][n][3]);
        }
    }
}

// ---------------- fp32 -> bf16 hi/lo split (inputs & weights) ---------------
__global__ void k_split(const float* __restrict__ src, __nv_bfloat16* __restrict__ hi,
                        __nv_bfloat16* __restrict__ lo, int n4)
{
    int i = blockIdx.x * blockDim.x + threadIdx.x;
    if (i >= n4) return;
    float4 v = ((const float4*)src)[i];
    uint2 hv, lv;
    hv.x = packbf(bf16rt(v.x), bf16rt(v.y));
    hv.y = packbf(bf16rt(v.z), bf16rt(v.w));
    lv.x = packbf(v.x - bf16rt(v.x), v.y - bf16rt(v.y));
    lv.y = packbf(v.z - bf16rt(v.z), v.w - bf16rt(v.w));
    ((uint2*)hi)[i] = hv;
    ((uint2*)lo)[i] = lv;
}

// ---------------- RoPE on Q -> QKVh/QKVl directly ---------------------------
__global__ void k_rope_q(const float* __restrict__ freqs,
                         __nv_bfloat16* __restrict__ QKVh, __nv_bfloat16* __restrict__ QKVl)
{
    int idx = blockIdx.x*blockDim.x + threadIdx.x;
    int i = idx & 63;
    int h = (idx >> 6) & (NH-1);
    int m = idx >> 10;
    int s = m & (SEQ-1);
    float f = freqs[(size_t)s*64 + i];
    float sn, cs; sincosf(f, &sn, &cs);
    size_t off = (size_t)m*QKVDIM + h*HD + 2*i;
    float2 v = *(float2*)(g_QKV + off);
    float rx = v.x*cs - v.y*sn;
    float ry = v.x*sn + v.y*cs;
    *(uint32_t*)&QKVh[off] = packbf(bf16rt(rx), bf16rt(ry));
    *(uint32_t*)&QKVl[off] = packbf(rx - bf16rt(rx), ry - bf16rt(ry));
}

// ---------------- RoPE on K -> QKVh/QKVl + new_k ----------------------------
__global__ void k_rope_k(const float* __restrict__ freqs, float* __restrict__ outk,
                         __nv_bfloat16* __restrict__ QKVh, __nv_bfloat16* __restrict__ QKVl)
{
    int idx = blockIdx.x*blockDim.x + threadIdx.x;
    int i = idx & 63;
    int h = (idx >> 6) & (NKV-1);
    int m = idx >> 8;
    int s = m & (SEQ-1);
    float f = freqs[(size_t)s*64 + i];
    float sn, cs; sincosf(f, &sn, &cs);
    size_t off = (size_t)m*QKVDIM + QDIM + h*HD + 2*i;
    float2 v = *(float2*)(g_QKV + off);
    float rx = v.x*cs - v.y*sn;
    float ry = v.x*sn + v.y*cs;
    *(uint32_t*)&QKVh[off] = packbf(bf16rt(rx), bf16rt(ry));
    *(uint32_t*)&QKVl[off] = packbf(rx - bf16rt(rx), ry - bf16rt(ry));
    *(float2*)(outk + (size_t)m*KVDIM + h*HD + 2*i) = make_float2(rx, ry);
}

// ---------------- V -> new_v + QKVh/QKVl ------------------------------------
__global__ void k_copy_v(float* __restrict__ outv,
                         __nv_bfloat16* __restrict__ QKVh, __nv_bfloat16* __restrict__ QKVl)
{
    int idx = blockIdx.x*blockDim.x + threadIdx.x;
    int m = idx >> 7, c = (idx & 127) * 4;
    size_t off = (size_t)m*QKVDIM + QDIM + KVDIM + c;
    float4 v = *(const float4*)(g_QKV + off);
    *(float4*)(outv + (size_t)m*KVDIM + c) = v;
    uint2 hv, lv;
    hv.x = packbf(bf16rt(v.x), bf16rt(v.y));
    hv.y = packbf(bf16rt(v.z), bf16rt(v.w));
    lv.x = packbf(v.x - bf16rt(v.x), v.y - bf16rt(v.y));
    lv.y = packbf(v.z - bf16rt(v.z), v.w - bf16rt(v.w));
    *(uint2*)&QKVh[off] = hv;
    *(uint2*)&QKVl[off] = lv;
}

// ============ fused flash attention (HMMA, cp.async phase pipeline) ==========
#define TILE_B 34816     // 128 * 136 * 2 bytes
#define FLASH_SMEM (6 * TILE_B)

__global__ void __launch_bounds__(256, 1) k_flash(
    const __nv_bfloat16* __restrict__ QKVh, const __nv_bfloat16* __restrict__ QKVl,
    __nv_bfloat16* __restrict__ AOh, __nv_bfloat16* __restrict__ AOl)
{
    extern __shared__ char smraw[];
    typedef __nv_bfloat16 (*tile_t)[136];
    tile_t sQh = (tile_t)(smraw);
    tile_t sQl = (tile_t)(smraw + 1*TILE_B);
    tile_t sKh = (tile_t)(smraw + 2*TILE_B);
    tile_t sKl = (tile_t)(smraw + 3*TILE_B);
    tile_t sVh = (tile_t)(smraw + 4*TILE_B);
    tile_t sVl = (tile_t)(smraw + 5*TILE_B);

    const int qt = (int)gridDim.x - 1 - (int)blockIdx.x;   // heavy tiles first
    const int bh = blockIdx.y;
    const int b = bh >> 4, h = bh & 15, kh = h >> 2;
    const int tid = threadIdx.x, lane = tid & 31, wid = tid >> 5;

    auto load_tile = [&](tile_t dst, const __nv_bfloat16* src) {
        #pragma unroll
        for (int u = 0; u < 8; u++) {
            int i = tid + u * 256;
            int r = i >> 4, c = (i & 15) * 8;
            CP_ASYNC16(smem_u32(&dst[r][c]), src + (size_t)r*QKVDIM + c);
        }
    };

    const size_t qbase = ((size_t)(b*SEQ + qt*128))*QKVDIM + h*HD;
    load_tile(sQh, QKVh + qbase); load_tile(sQl, QKVl + qbase); CP_COMMIT();
    {
        const size_t kb = ((size_t)(b*SEQ))*QKVDIM + QDIM + kh*HD;
        load_tile(sKh, QKVh + kb); load_tile(sKl, QKVl + kb); CP_COMMIT();
        load_tile(sVh, QKVh + kb + KVDIM); load_tile(sVl, QKVl + kb + KVDIM); CP_COMMIT();
    }

    float oacc[16][4];
    #pragma unroll
    for (int n = 0; n < 16; n++)
        #pragma unroll
        for (int i = 0; i < 4; i++) oacc[n][i] = 0.f;
    float mi0 = -1e30f, mi1 = -1e30f, li0 = 0.f, li1 = 0.f;

    const int q_r  = wid*16 + (lane & 15);
    const int q_c  = (lane >> 4) * 8;
    const int k_ro = ((lane >> 4) & 1) * 8 + (lane & 7);
    const int k_co = ((lane >> 3) & 1) * 8;
    const int v_ro = ((lane >> 3) & 1) * 8 + (lane & 7);
    const int v_co = ((lane >> 4) & 1) * 8;
    const int r_lo = lane >> 2;
    const int c_lo = (lane & 3) * 2;

    for (int kt = 0; kt <= qt; kt++) {
        CP_WAIT1();          // Q + K[kt] resident (V[kt] may be in flight)
        __syncthreads();

        float sacc[16][4];
        #pragma unroll
        for (int n = 0; n < 16; n++)
            #pragma unroll
            for (int i = 0; i < 4; i++) sacc[n][i] = 0.f;

        #pragma unroll
        for (int kk = 0; kk < 8; kk++) {
            uint32_t ah[4], al[4];
            ldsm_x4(ah, smem_u32(&sQh[q_r][kk*16 + q_c]));
            ldsm_x4(al, smem_u32(&sQl[q_r][kk*16 + q_c]));
            #pragma unroll
            for (int j2 = 0; j2 < 8; j2++) {
                uint32_t kb[4], klb[4];
                ldsm_x4(kb,  smem_u32(&sKh[16*j2 + k_ro][kk*16 + k_co]));
                ldsm_x4(klb, smem_u32(&sKl[16*j2 + k_ro][kk*16 + k_co]));
                mma16816(sacc[2*j2],   ah, kb);
                mma16816(sacc[2*j2],   ah, klb);
                mma16816(sacc[2*j2],   al, kb);
                mma16816(sacc[2*j2+1], ah, kb + 2);
                mma16816(sacc[2*j2+1], ah, klb + 2);
                mma16816(sacc[2*j2+1], al, kb + 2);
            }
        }
        __syncthreads();      // sK free

        if (kt < qt) {        // prefetch next K, overlaps softmax + PV
            const size_t kb = ((size_t)(b*SEQ + (kt+1)*128))*QKVDIM + QDIM + kh*HD;
            load_tile(sKh, QKVh + kb); load_tile(sKl, QKVl + kb); CP_COMMIT();
        }

        const bool diag = (kt == qt);
        float mx0 = -1e30f, mx1 = -1e30f;
        #pragma unroll
        for (int n = 0; n < 16; n++) {
            float e0 = sacc[n][0]*CS, e1 = sacc[n][1]*CS;
            float e2 = sacc[n][2]*CS, e3 = sacc[n][3]*CS;
            if (diag) {
                int c0 = n*8 + c_lo;
                int r0 = wid*16 + r_lo;
                if (c0     > r0)     e0 = -1e30f;
                if (c0 + 1 > r0)     e1 = -1e30f;
                if (c0     > r0 + 8) e2 = -1e30f;
                if (c0 + 1 > r0 + 8) e3 = -1e30f;
            }
            sacc[n][0] = e0; sacc[n][1] = e1; sacc[n][2] = e2; sacc[n][3] = e3;
            mx0 = fmaxf(mx0, fmaxf(e0, e1));
            mx1 = fmaxf(mx1, fmaxf(e2, e3));
        }
        mx0 = fmaxf(mx0, __shfl_xor_sync(0xffffffffu, mx0, 1));
        mx0 = fmaxf(mx0, __shfl_xor_sync(0xffffffffu, mx0, 2));
        mx1 = fmaxf(mx1, __shfl_xor_sync(0xffffffffu, mx1, 1));
        mx1 = fmaxf(mx1, __shfl_xor_sync(0xffffffffu, mx1, 2));

        float mn0 = fmaxf(mi0, mx0), mn1 = fmaxf(mi1, mx1);
        float al0 = ex2f(mi0 - mn0), al1 = ex2f(mi1 - mn1);
        mi0 = mn0; mi1 = mn1;

        float s0 = 0.f, s1 = 0.f;
        #pragma unroll
        for (int n = 0; n < 16; n++) {
            float p0 = ex2f(sacc[n][0] - mn0), p1 = ex2f(sacc[n][1] - mn0);
            float p2 = ex2f(sacc[n][2] - mn1), p3 = ex2f(sacc[n][3] - mn1);
            sacc[n][0] = p0; sacc[n][1] = p1; sacc[n][2] = p2; sacc[n][3] = p3;
            s0 += p0 + p1; s1 += p2 + p3;
        }
        s0 += __shfl_xor_sync(0xffffffffu, s0, 1);
        s0 += __shfl_xor_sync(0xffffffffu, s0, 2);
        s1 += __shfl_xor_sync(0xffffffffu, s1, 1);
        s1 += __shfl_xor_sync(0xffffffffu, s1, 2);
        li0 = li0 * al0 + s0;
        li1 = li1 * al1 + s1;

        #pragma unroll
        for (int n = 0; n < 16; n++) {
            oacc[n][0] *= al0; oacc[n][1] *= al0;
            oacc[n][2] *= al1; oacc[n][3] *= al1;
        }

        if (kt < qt) CP_WAIT1(); else CP_WAIT0();   // V[kt] resident
        __syncthreads();

        #pragma unroll
        for (int kk2 = 0; kk2 < 8; kk2++) {
            float p00 = sacc[2*kk2][0],   p01 = sacc[2*kk2][1];
            float p02 = sacc[2*kk2][2],   p03 = sacc[2*kk2][3];
            float p10 = sacc[2*kk2+1][0], p11 = sacc[2*kk2+1][1];
            float p12 = sacc[2*kk2+1][2], p13 = sacc[2*kk2+1][3];
            uint32_t pah[4], pal[4];
            pah[0] = packbf(p00, p01); pah[1] = packbf(p02, p03);
            pah[2] = packbf(p10, p11); pah[3] = packbf(p12, p13);
            pal[0] = packbf(p00 - bf16rt(p00), p01 - bf16rt(p01));
            pal[1] = packbf(p02 - bf16rt(p02), p03 - bf16rt(p03));
            pal[2] = packbf(p10 - bf16rt(p10), p11 - bf16rt(p11));
            pal[3] = packbf(p12 - bf16rt(p12), p13 - bf16rt(p13));

            #pragma unroll
            for (int j = 0; j < 8; j++) {
                uint32_t vb[4], vlb[4];
                ldsm_x4_t(vb,  smem_u32(&sVh[kk2*16 + v_ro][16*j + v_co]));
                ldsm_x4_t(vlb, smem_u32(&sVl[kk2*16 + v_ro][16*j + v_co]));
                mma16816(oacc[2*j],   pah, vb);
                mma16816(oacc[2*j],   pah, vlb);
                mma16816(oacc[2*j],   pal, vb);
                mma16816(oacc[2*j+1], pah, vb + 2);
                mma16816(oacc[2*j+1], pah, vlb + 2);
                mma16816(oacc[2*j+1], pal, vb + 2);
            }
        }
        __syncthreads();      // sV free

        if (kt < qt) {        // prefetch next V, overlaps next S
            const size_t vb = ((size_t)(b*SEQ + (kt+1)*128))*QKVDIM + QDIM + KVDIM + kh*HD;
            load_tile(sVh, QKVh + vb); load_tile(sVl, QKVl + vb); CP_COMMIT();
        }
    }

    float inv0 = 1.f / li0, inv1 = 1.f / li1;
    size_t row0 = (size_t)(b*SEQ + qt*128 + wid*16 + r_lo);
    size_t colb = (size_t)h*HD + c_lo;
    #pragma unroll
    for (int n = 0; n < 16; n++) {
        float v0 = oacc[n][0]*inv0, v1 = oacc[n][1]*inv0;
        float v2 = oacc[n][2]*inv1, v3 = oacc[n][3]*inv1;
        size_t o0 = row0*QDIM + colb + n*8;
        size_t o1 = (row0+8)*QDIM + colb + n*8;
        *(uint32_t*)&AOh[o0] = packbf(bf16rt(v0), bf16rt(v1));
        *(uint32_t*)&AOl[o0] = packbf(v0 - bf16rt(v0), v1 - bf16rt(v1));
        *(uint32_t*)&AOh[o1] = packbf(bf16rt(v2), bf16rt(v3));
        *(uint32_t*)&AOl[o1] = packbf(v2 - bf16rt(v2), v3 - bf16rt(v3));
    }
}

// ---------------- launch -----------------------------------------------------
extern "C" void kernel_launch(void* const* d_in, const int* in_sizes, int n_in,
                              void* d_out, int out_size)
{
    const float* x     = (const float*)d_in[0];
    const float* wq    = (const float*)d_in[1];
    const float* wk    = (const float*)d_in[2];
    const float* wv    = (const float*)d_in[3];
    const float* wo    = (const float*)d_in[4];
    const float* freqs = (const float*)d_in[5];
    (void)in_sizes; (void)n_in; (void)out_size;

    float* out  = (float*)d_out;
    float* outk = out  + (size_t)MTOT*HIDDEN;
    float* outv = outk + (size_t)MTOT*KVDIM;

    float *QKVp;
    __nv_bfloat16 *Xh, *Xl, *Wh, *Wl, *WOh, *WOl, *AOh, *AOl, *QKVh, *QKVl;
    cudaGetSymbolAddress((void**)&QKVp, g_QKV);
    cudaGetSymbolAddress((void**)&Xh,   g_Xh);
    cudaGetSymbolAddress((void**)&Xl,   g_Xl);
    cudaGetSymbolAddress((void**)&Wh,   g_Wh);
    cudaGetSymbolAddress((void**)&Wl,   g_Wl);
    cudaGetSymbolAddress((void**)&WOh,  g_WOh);
    cudaGetSymbolAddress((void**)&WOl,  g_WOl);
    cudaGetSymbolAddress((void**)&AOh,  g_AOh);
    cudaGetSymbolAddress((void**)&AOl,  g_AOl);
    cudaGetSymbolAddress((void**)&QKVh, g_QKVh);
    cudaGetSymbolAddress((void**)&QKVl, g_QKVl);

    cudaFuncSetAttribute(k_flash,  cudaFuncAttributeMaxDynamicSharedMemorySize, FLASH_SMEM);
    cudaFuncSetAttribute(mma_gemm, cudaFuncAttributeMaxDynamicSharedMemorySize, GEMM_SMEM);

    k_split<<<(MTOT*HIDDEN/4 + 255)/256, 256>>>(x,  Xh, Xl, MTOT*HIDDEN/4);
    k_split<<<(QDIM*HIDDEN/4 + 255)/256, 256>>>(wq, Wh, Wl, QDIM*HIDDEN/4);
    k_split<<<(KVDIM*HIDDEN/4 + 255)/256, 256>>>(wk, Wh + (size_t)QDIM*HIDDEN,
                                                 Wl + (size_t)QDIM*HIDDEN, KVDIM*HIDDEN/4);
    k_split<<<(KVDIM*HIDDEN/4 + 255)/256, 256>>>(wv, Wh + (size_t)(QDIM+KVDIM)*HIDDEN,
                                                 Wl + (size_t)(QDIM+KVDIM)*HIDDEN, KVDIM*HIDDEN/4);
    k_split<<<(HIDDEN*QDIM/4 + 255)/256, 256>>>(wo, WOh, WOl, HIDDEN*QDIM/4);

    mma_gemm<<<dim3(QKVDIM/128, MTOT/128), 256, GEMM_SMEM>>>(Xh, Xl, Wh, Wl, QKVp, QKVDIM, HIDDEN);

    k_rope_q<<<(MTOT*NH *64)/256, 256>>>(freqs, QKVh, QKVl);
    k_rope_k<<<(MTOT*NKV*64)/256, 256>>>(freqs, outk, QKVh, QKVl);
    k_copy_v<<<(MTOT*KVDIM/4)/256, 256>>>(outv, QKVh, QKVl);

    k_flash<<<dim3(SEQ/128, BATCH*NH), 256, FLASH_SMEM>>>(QKVh, QKVl, AOh, AOl);

    mma_gemm<<<dim3(HIDDEN/128, MTOT/128), 256, GEMM_SMEM>>>(AOh, AOl, WOh, WOl, out, HIDDEN, QDIM);
}

// round 16
// speedup vs baseline: 3.2643x; 1.0265x over previous
#include <cuda_runtime.h>
#include <cuda_bf16.h>
#include <math.h>
#include <stdint.h>

#define BATCH   2
#define SEQ     2048
#define HIDDEN  2048
#define NH      16
#define NKV     4
#define HD      128
#define MTOT    (BATCH*SEQ)      // 4096
#define QDIM    (NH*HD)          // 2048
#define KVDIM   (NKV*HD)         // 512
#define QKVDIM  (QDIM+2*KVDIM)   // 3072
#define ATTN_SCALE 0.08838834764831845f
#define CS (ATTN_SCALE * 1.4426950408889634f)   // scale * log2(e)

// ---------------- scratch (device globals; no allocation allowed) ----------
__device__ __nv_bfloat16 g_Xh[(size_t)MTOT*HIDDEN];
__device__ __nv_bfloat16 g_Xl[(size_t)MTOT*HIDDEN];
__device__ __nv_bfloat16 g_Wh[(size_t)QKVDIM*HIDDEN];
__device__ __nv_bfloat16 g_Wl[(size_t)QKVDIM*HIDDEN];
__device__ __nv_bfloat16 g_WOh[(size_t)HIDDEN*QDIM];
__device__ __nv_bfloat16 g_WOl[(size_t)HIDDEN*QDIM];
__device__ __nv_bfloat16 g_QKVh[(size_t)MTOT*QKVDIM];   // 25 MB
__device__ __nv_bfloat16 g_QKVl[(size_t)MTOT*QKVDIM];
__device__ __nv_bfloat16 g_AOh[(size_t)MTOT*QDIM];
__device__ __nv_bfloat16 g_AOl[(size_t)MTOT*QDIM];

// ================= helpers ==================================================
__device__ __forceinline__ void ldsm_x4(uint32_t* r, uint32_t addr) {
    asm volatile("ldmatrix.sync.aligned.m8n8.x4.shared.b16 {%0,%1,%2,%3}, [%4];"
                 : "=r"(r[0]), "=r"(r[1]), "=r"(r[2]), "=r"(r[3]) : "r"(addr));
}
__device__ __forceinline__ void ldsm_x4_t(uint32_t* r, uint32_t addr) {
    asm volatile("ldmatrix.sync.aligned.m8n8.x4.trans.shared.b16 {%0,%1,%2,%3}, [%4];"
                 : "=r"(r[0]), "=r"(r[1]), "=r"(r[2]), "=r"(r[3]) : "r"(addr));
}
__device__ __forceinline__ void mma16816(float* d, const uint32_t* a, const uint32_t* b) {
    asm volatile("mma.sync.aligned.m16n8k16.row.col.f32.bf16.bf16.f32 "
                 "{%0,%1,%2,%3},{%4,%5,%6,%7},{%8,%9},{%0,%1,%2,%3};"
                 : "+f"(d[0]), "+f"(d[1]), "+f"(d[2]), "+f"(d[3])
                 : "r"(a[0]), "r"(a[1]), "r"(a[2]), "r"(a[3]), "r"(b[0]), "r"(b[1]));
}
__device__ __forceinline__ uint32_t smem_u32(const void* p) {
    return (uint32_t)__cvta_generic_to_shared(p);
}
__device__ __forceinline__ float ex2f(float x) {
    float r; asm("ex2.approx.ftz.f32 %0, %1;" : "=f"(r) : "f"(x)); return r;
}
__device__ __forceinline__ uint32_t packbf(float lo, float hi) {  // lo -> low half
    uint32_t d; asm("cvt.rn.bf16x2.f32 %0, %1, %2;" : "=r"(d) : "f"(hi), "f"(lo)); return d;
}
__device__ __forceinline__ float bf16rt(float x) {
    return __bfloat162float(__float2bfloat16(x));
}
#define CP_ASYNC16(sa, gp) \
    asm volatile("cp.async.cg.shared.global [%0], [%1], 16;" :: "r"(sa), "l"(gp))
#define CP_COMMIT() asm volatile("cp.async.commit_group;" ::: "memory")
#define CP_WAIT0()  asm volatile("cp.async.wait_group 0;" ::: "memory")
#define CP_WAIT1()  asm volatile("cp.async.wait_group 1;" ::: "memory")

// ============ HMMA GEMM, 2-stage cp.async pipeline ==========================
// FUSE=false: plain C[M,N] fp32 store.
// FUSE=true : QKV epilogue — RoPE on Q/K sections, emit new_k/new_v,
//             write bf16 hi/lo QKV directly. (C/ldc unused.)
#define BK    32
#define SLD   40
#define TILE_HALVES  (128*SLD)
#define STAGE_HALVES (4*TILE_HALVES)
#define GEMM_SMEM    (2*STAGE_HALVES*2)   // 81920 bytes

template<bool FUSE>
__global__ void __launch_bounds__(256, 2) mma_gemm(
    const __nv_bfloat16* __restrict__ Ah, const __nv_bfloat16* __restrict__ Al,
    const __nv_bfloat16* __restrict__ Bh, const __nv_bfloat16* __restrict__ Bl,
    float* __restrict__ C, int ldc, int K,
    const float* __restrict__ freqs, float* __restrict__ outk, float* __restrict__ outv,
    __nv_bfloat16* __restrict__ Oh, __nv_bfloat16* __restrict__ Ol)
{
    extern __shared__ __nv_bfloat16 sm[];
    const int tid  = threadIdx.x;
    const int lane = tid & 31;
    const int wid  = tid >> 5;
    const int wr   = wid >> 2;
    const int wc   = wid & 3;

    float acc[4][4][4];
    #pragma unroll
    for (int m = 0; m < 4; m++)
        #pragma unroll
        for (int n = 0; n < 4; n++)
            #pragma unroll
            for (int i = 0; i < 4; i++) acc[m][n][i] = 0.f;

    const size_t arow0 = (size_t)blockIdx.y * 128;
    const size_t brow0 = (size_t)blockIdx.x * 128;

    const int a_r = lane & 15, a_c = ((lane >> 4) & 1) * 8;
    const int b_r = ((lane >> 4) & 1) * 8 + (lane & 7);   // n-pair ldsm_x4 pattern
    const int b_c = ((lane >> 3) & 1) * 8;
    const int nk = K / BK;

    auto issue_stage = [&](int sel, int k0) {
        __nv_bfloat16* base = sm + sel * STAGE_HALVES;
        const __nv_bfloat16* srcs[4] = { Ah + arow0*K + k0, Al + arow0*K + k0,
                                         Bh + brow0*K + k0, Bl + brow0*K + k0 };
        #pragma unroll
        for (int t = 0; t < 4; t++) {
            __nv_bfloat16* dst = base + t * TILE_HALVES;
            #pragma unroll
            for (int u = 0; u < 2; u++) {
                int idx = tid + u * 256;
                int r = idx >> 2, c = (idx & 3) * 8;
                CP_ASYNC16(smem_u32(dst + r*SLD + c), srcs[t] + (size_t)r*K + c);
            }
        }
        CP_COMMIT();
    };

    issue_stage(0, 0);
    for (int i = 0; i < nk; i++) {
        if (i + 1 < nk) { issue_stage((i + 1) & 1, (i + 1) * BK); CP_WAIT1(); }
        else            { CP_WAIT0(); }
        __syncthreads();

        __nv_bfloat16* base = sm + (i & 1) * STAGE_HALVES;
        __nv_bfloat16* bAh = base;
        __nv_bfloat16* bAl = base + 1*TILE_HALVES;
        __nv_bfloat16* bBh = base + 2*TILE_HALVES;
        __nv_bfloat16* bBl = base + 3*TILE_HALVES;

        #pragma unroll
        for (int kk = 0; kk < BK; kk += 16) {
            uint32_t bhf[4][2], blf[4][2];
            #pragma unroll
            for (int np = 0; np < 4; np += 2) {
                int row = wc * 32 + np * 8 + b_r;
                uint32_t t4[4];
                ldsm_x4(t4, smem_u32(bBh + row*SLD + kk + b_c));
                bhf[np][0] = t4[0]; bhf[np][1] = t4[1];
                bhf[np+1][0] = t4[2]; bhf[np+1][1] = t4[3];
                ldsm_x4(t4, smem_u32(bBl + row*SLD + kk + b_c));
                blf[np][0] = t4[0]; blf[np][1] = t4[1];
                blf[np+1][0] = t4[2]; blf[np+1][1] = t4[3];
            }
            #pragma unroll
            for (int m = 0; m < 4; m++) {
                uint32_t ah[4], al[4];
                int row = wr * 64 + m * 16 + a_r;
                ldsm_x4(ah, smem_u32(bAh + row*SLD + kk + a_c));
                ldsm_x4(al, smem_u32(bAl + row*SLD + kk + a_c));
                #pragma unroll
                for (int n = 0; n < 4; n++) {
                    mma16816(acc[m][n], ah, bhf[n]);
                    mma16816(acc[m][n], ah, blf[n]);
                    mma16816(acc[m][n], al, bhf[n]);
                }
            }
        }
        __syncthreads();
    }

    const int r0 = lane >> 2, cbase = (lane & 3) * 2;
    #pragma unroll
    for (int m = 0; m < 4; m++) {
        size_t grow = arow0 + wr * 64 + m * 16 + r0;
        #pragma unroll
        for (int n = 0; n < 4; n++) {
            int gcol = (int)brow0 + wc * 32 + n * 8 + cbase;
            if (!FUSE) {
                *(float2*)(C + grow * ldc + gcol)       = make_float2(acc[m][n][0], acc[m][n][1]);
                *(float2*)(C + (grow + 8) * ldc + gcol) = make_float2(acc[m][n][2], acc[m][n][3]);
            } else {
                #pragma unroll
                for (int half = 0; half < 2; half++) {
                    size_t row = grow + half * 8;
                    float v0 = acc[m][n][half*2], v1 = acc[m][n][half*2 + 1];
                    float rx = v0, ry = v1;
                    if (gcol < QDIM + KVDIM) {          // Q or K: apply RoPE
                        int s = (int)(row & (SEQ - 1));
                        int fi = (gcol & (HD - 1)) >> 1;
                        float f = freqs[(size_t)s*64 + fi];
                        float sn, cc; sincosf(f, &sn, &cc);
                        rx = v0*cc - v1*sn;
                        ry = v0*sn + v1*cc;
                        if (gcol >= QDIM)               // K: emit new_k (fp32)
                            *(float2*)(outk + row*KVDIM + (gcol - QDIM)) = make_float2(rx, ry);
                    } else {                            // V: emit new_v (fp32)
                        *(float2*)(outv + row*KVDIM + (gcol - QDIM - KVDIM)) = make_float2(v0, v1);
                    }
                    *(uint32_t*)&Oh[row*QKVDIM + gcol] = packbf(bf16rt(rx), bf16rt(ry));
                    *(uint32_t*)&Ol[row*QKVDIM + gcol] = packbf(rx - bf16rt(rx), ry - bf16rt(ry));
                }
            }
        }
    }
}

// ---------------- fused fp32 -> bf16 hi/lo split of all 5 inputs -------------
#define N4_X   (MTOT*HIDDEN/4)       // 2097152
#define N4_WQ  (QDIM*HIDDEN/4)       // 1048576
#define N4_WKV (KVDIM*HIDDEN/4)      // 262144
#define N4_WO  (HIDDEN*QDIM/4)       // 1048576
#define N4_TOT (N4_X + N4_WQ + 2*N4_WKV + N4_WO)   // 4718592

__global__ void k_split_all(const float* __restrict__ x,  const float* __restrict__ wq,
                            const float* __restrict__ wk, const float* __restrict__ wv,
                            const float* __restrict__ wo,
                            __nv_bfloat16* __restrict__ Xh, __nv_bfloat16* __restrict__ Xl,
                            __nv_bfloat16* __restrict__ Wh, __nv_bfloat16* __restrict__ Wl,
                            __nv_bfloat16* __restrict__ WOh, __nv_bfloat16* __restrict__ WOl)
{
    int i = blockIdx.x * blockDim.x + threadIdx.x;
    if (i >= N4_TOT) return;
    const float* src; __nv_bfloat16 *hi, *lo; int j = i;
    if (j < N4_X)                       { src = x;  hi = Xh; lo = Xl; }
    else if ((j -= N4_X)  < N4_WQ)      { src = wq; hi = Wh; lo = Wl; }
    else if ((j -= N4_WQ) < N4_WKV)     { src = wk; hi = Wh + (size_t)QDIM*HIDDEN;
                                                    lo = Wl + (size_t)QDIM*HIDDEN; }
    else if ((j -= N4_WKV) < N4_WKV)    { src = wv; hi = Wh + (size_t)(QDIM+KVDIM)*HIDDEN;
                                                    lo = Wl + (size_t)(QDIM+KVDIM)*HIDDEN; }
    else                                { j -= N4_WKV; src = wo; hi = WOh; lo = WOl; }
    float4 v = ((const float4*)src)[j];
    uint2 hv, lv;
    hv.x = packbf(bf16rt(v.x), bf16rt(v.y));
    hv.y = packbf(bf16rt(v.z), bf16rt(v.w));
    lv.x = packbf(v.x - bf16rt(v.x), v.y - bf16rt(v.y));
    lv.y = packbf(v.z - bf16rt(v.z), v.w - bf16rt(v.w));
    ((uint2*)hi)[j] = hv;
    ((uint2*)lo)[j] = lv;
}

// ============ fused flash attention (HMMA, cp.async phase pipeline) ==========
#define TILE_B 34816     // 128 * 136 * 2 bytes
#define FLASH_SMEM (6 * TILE_B)

__global__ void __launch_bounds__(256, 1) k_flash(
    const __nv_bfloat16* __restrict__ QKVh, const __nv_bfloat16* __restrict__ QKVl,
    __nv_bfloat16* __restrict__ AOh, __nv_bfloat16* __restrict__ AOl)
{
    extern __shared__ char smraw[];
    typedef __nv_bfloat16 (*tile_t)[136];
    tile_t sQh = (tile_t)(smraw);
    tile_t sQl = (tile_t)(smraw + 1*TILE_B);
    tile_t sKh = (tile_t)(smraw + 2*TILE_B);
    tile_t sKl = (tile_t)(smraw + 3*TILE_B);
    tile_t sVh = (tile_t)(smraw + 4*TILE_B);
    tile_t sVl = (tile_t)(smraw + 5*TILE_B);

    const int qt = (int)gridDim.x - 1 - (int)blockIdx.x;   // heavy tiles first
    const int bh = blockIdx.y;
    const int b = bh >> 4, h = bh & 15, kh = h >> 2;
    const int tid = threadIdx.x, lane = tid & 31, wid = tid >> 5;

    auto load_tile = [&](tile_t dst, const __nv_bfloat16* src) {
        #pragma unroll
        for (int u = 0; u < 8; u++) {
            int i = tid + u * 256;
            int r = i >> 4, c = (i & 15) * 8;
            CP_ASYNC16(smem_u32(&dst[r][c]), src + (size_t)r*QKVDIM + c);
        }
    };

    const size_t qbase = ((size_t)(b*SEQ + qt*128))*QKVDIM + h*HD;
    load_tile(sQh, QKVh + qbase); load_tile(sQl, QKVl + qbase); CP_COMMIT();
    {
        const size_t kb = ((size_t)(b*SEQ))*QKVDIM + QDIM + kh*HD;
        load_tile(sKh, QKVh + kb); load_tile(sKl, QKVl + kb); CP_COMMIT();
        load_tile(sVh, QKVh + kb + KVDIM); load_tile(sVl, QKVl + kb + KVDIM); CP_COMMIT();
    }

    float oacc[16][4];
    #pragma unroll
    for (int n = 0; n < 16; n++)
        #pragma unroll
        for (int i = 0; i < 4; i++) oacc[n][i] = 0.f;
    float mi0 = -1e30f, mi1 = -1e30f, li0 = 0.f, li1 = 0.f;

    const int q_r  = wid*16 + (lane & 15);
    const int q_c  = (lane >> 4) * 8;
    const int k_ro = ((lane >> 4) & 1) * 8 + (lane & 7);
    const int k_co = ((lane >> 3) & 1) * 8;
    const int v_ro = ((lane >> 3) & 1) * 8 + (lane & 7);
    const int v_co = ((lane >> 4) & 1) * 8;
    const int r_lo = lane >> 2;
    const int c_lo = (lane & 3) * 2;

    for (int kt = 0; kt <= qt; kt++) {
        CP_WAIT1();          // Q + K[kt] resident (V[kt] may be in flight)
        __syncthreads();

        float sacc[16][4];
        #pragma unroll
        for (int n = 0; n < 16; n++)
            #pragma unroll
            for (int i = 0; i < 4; i++) sacc[n][i] = 0.f;

        #pragma unroll
        for (int kk = 0; kk < 8; kk++) {
            uint32_t ah[4], al[4];
            ldsm_x4(ah, smem_u32(&sQh[q_r][kk*16 + q_c]));
            ldsm_x4(al, smem_u32(&sQl[q_r][kk*16 + q_c]));
            #pragma unroll
            for (int j2 = 0; j2 < 8; j2++) {
                uint32_t kb[4], klb[4];
                ldsm_x4(kb,  smem_u32(&sKh[16*j2 + k_ro][kk*16 + k_co]));
                ldsm_x4(klb, smem_u32(&sKl[16*j2 + k_ro][kk*16 + k_co]));
                mma16816(sacc[2*j2],   ah, kb);
                mma16816(sacc[2*j2],   ah, klb);
                mma16816(sacc[2*j2],   al, kb);
                mma16816(sacc[2*j2+1], ah, kb + 2);
                mma16816(sacc[2*j2+1], ah, klb + 2);
                mma16816(sacc[2*j2+1], al, kb + 2);
            }
        }
        __syncthreads();      // sK free

        if (kt < qt) {        // prefetch next K, overlaps softmax + PV
            const size_t kb = ((size_t)(b*SEQ + (kt+1)*128))*QKVDIM + QDIM + kh*HD;
            load_tile(sKh, QKVh + kb); load_tile(sKl, QKVl + kb); CP_COMMIT();
        }

        const bool diag = (kt == qt);
        float mx0 = -1e30f, mx1 = -1e30f;
        #pragma unroll
        for (int n = 0; n < 16; n++) {
            float e0 = sacc[n][0]*CS, e1 = sacc[n][1]*CS;
            float e2 = sacc[n][2]*CS, e3 = sacc[n][3]*CS;
            if (diag) {
                int c0 = n*8 + c_lo;
                int rr = wid*16 + r_lo;
                if (c0     > rr)     e0 = -1e30f;
                if (c0 + 1 > rr)     e1 = -1e30f;
                if (c0     > rr + 8) e2 = -1e30f;
                if (c0 + 1 > rr + 8) e3 = -1e30f;
            }
            sacc[n][0] = e0; sacc[n][1] = e1; sacc[n][2] = e2; sacc[n][3] = e3;
            mx0 = fmaxf(mx0, fmaxf(e0, e1));
            mx1 = fmaxf(mx1, fmaxf(e2, e3));
        }
        mx0 = fmaxf(mx0, __shfl_xor_sync(0xffffffffu, mx0, 1));
        mx0 = fmaxf(mx0, __shfl_xor_sync(0xffffffffu, mx0, 2));
        mx1 = fmaxf(mx1, __shfl_xor_sync(0xffffffffu, mx1, 1));
        mx1 = fmaxf(mx1, __shfl_xor_sync(0xffffffffu, mx1, 2));

        float mn0 = fmaxf(mi0, mx0), mn1 = fmaxf(mi1, mx1);
        float al0 = ex2f(mi0 - mn0), al1 = ex2f(mi1 - mn1);
        mi0 = mn0; mi1 = mn1;

        float s0 = 0.f, s1 = 0.f;
        #pragma unroll
        for (int n = 0; n < 16; n++) {
            float p0 = ex2f(sacc[n][0] - mn0), p1 = ex2f(sacc[n][1] - mn0);
            float p2 = ex2f(sacc[n][2] - mn1), p3 = ex2f(sacc[n][3] - mn1);
            sacc[n][0] = p0; sacc[n][1] = p1; sacc[n][2] = p2; sacc[n][3] = p3;
            s0 += p0 + p1; s1 += p2 + p3;
        }
        s0 += __shfl_xor_sync(0xffffffffu, s0, 1);
        s0 += __shfl_xor_sync(0xffffffffu, s0, 2);
        s1 += __shfl_xor_sync(0xffffffffu, s1, 1);
        s1 += __shfl_xor_sync(0xffffffffu, s1, 2);
        li0 = li0 * al0 + s0;
        li1 = li1 * al1 + s1;

        #pragma unroll
        for (int n = 0; n < 16; n++) {
            oacc[n][0] *= al0; oacc[n][1] *= al0;
            oacc[n][2] *= al1; oacc[n][3] *= al1;
        }

        if (kt < qt) CP_WAIT1(); else CP_WAIT0();   // V[kt] resident
        __syncthreads();

        #pragma unroll
        for (int kk2 = 0; kk2 < 8; kk2++) {
            float p00 = sacc[2*kk2][0],   p01 = sacc[2*kk2][1];
            float p02 = sacc[2*kk2][2],   p03 = sacc[2*kk2][3];
            float p10 = sacc[2*kk2+1][0], p11 = sacc[2*kk2+1][1];
            float p12 = sacc[2*kk2+1][2], p13 = sacc[2*kk2+1][3];
            uint32_t pah[4], pal[4];
            pah[0] = packbf(p00, p01); pah[1] = packbf(p02, p03);
            pah[2] = packbf(p10, p11); pah[3] = packbf(p12, p13);
            pal[0] = packbf(p00 - bf16rt(p00), p01 - bf16rt(p01));
            pal[1] = packbf(p02 - bf16rt(p02), p03 - bf16rt(p03));
            pal[2] = packbf(p10 - bf16rt(p10), p11 - bf16rt(p11));
            pal[3] = packbf(p12 - bf16rt(p12), p13 - bf16rt(p13));

            #pragma unroll
            for (int j = 0; j < 8; j++) {
                uint32_t vb[4], vlb[4];
                ldsm_x4_t(vb,  smem_u32(&sVh[kk2*16 + v_ro][16*j + v_co]));
                ldsm_x4_t(vlb, smem_u32(&sVl[kk2*16 + v_ro][16*j + v_co]));
                mma16816(oacc[2*j],   pah, vb);
                mma16816(oacc[2*j],   pah, vlb);
                mma16816(oacc[2*j],   pal, vb);
                mma16816(oacc[2*j+1], pah, vb + 2);
                mma16816(oacc[2*j+1], pah, vlb + 2);
                mma16816(oacc[2*j+1], pal, vb + 2);
            }
        }
        __syncthreads();      // sV free

        if (kt < qt) {        // prefetch next V, overlaps next S
            const size_t vb = ((size_t)(b*SEQ + (kt+1)*128))*QKVDIM + QDIM + KVDIM + kh*HD;
            load_tile(sVh, QKVh + vb); load_tile(sVl, QKVl + vb); CP_COMMIT();
        }
    }

    float inv0 = 1.f / li0, inv1 = 1.f / li1;
    size_t row0 = (size_t)(b*SEQ + qt*128 + wid*16 + r_lo);
    size_t colb = (size_t)h*HD + c_lo;
    #pragma unroll
    for (int n = 0; n < 16; n++) {
        float v0 = oacc[n][0]*inv0, v1 = oacc[n][1]*inv0;
        float v2 = oacc[n][2]*inv1, v3 = oacc[n][3]*inv1;
        size_t o0 = row0*QDIM + colb + n*8;
        size_t o1 = (row0+8)*QDIM + colb + n*8;
        *(uint32_t*)&AOh[o0] = packbf(bf16rt(v0), bf16rt(v1));
        *(uint32_t*)&AOl[o0] = packbf(v0 - bf16rt(v0), v1 - bf16rt(v1));
        *(uint32_t*)&AOh[o1] = packbf(bf16rt(v2), bf16rt(v3));
        *(uint32_t*)&AOl[o1] = packbf(v2 - bf16rt(v2), v3 - bf16rt(v3));
    }
}

// ---------------- launch -----------------------------------------------------
extern "C" void kernel_launch(void* const* d_in, const int* in_sizes, int n_in,
                              void* d_out, int out_size)
{
    const float* x     = (const float*)d_in[0];
    const float* wq    = (const float*)d_in[1];
    const float* wk    = (const float*)d_in[2];
    const float* wv    = (const float*)d_in[3];
    const float* wo    = (const float*)d_in[4];
    const float* freqs = (const float*)d_in[5];
    (void)in_sizes; (void)n_in; (void)out_size;

    float* out  = (float*)d_out;
    float* outk = out  + (size_t)MTOT*HIDDEN;
    float* outv = outk + (size_t)MTOT*KVDIM;

    __nv_bfloat16 *Xh, *Xl, *Wh, *Wl, *WOh, *WOl, *AOh, *AOl, *QKVh, *QKVl;
    cudaGetSymbolAddress((void**)&Xh,   g_Xh);
    cudaGetSymbolAddress((void**)&Xl,   g_Xl);
    cudaGetSymbolAddress((void**)&Wh,   g_Wh);
    cudaGetSymbolAddress((void**)&Wl,   g_Wl);
    cudaGetSymbolAddress((void**)&WOh,  g_WOh);
    cudaGetSymbolAddress((void**)&WOl,  g_WOl);
    cudaGetSymbolAddress((void**)&AOh,  g_AOh);
    cudaGetSymbolAddress((void**)&AOl,  g_AOl);
    cudaGetSymbolAddress((void**)&QKVh, g_QKVh);
    cudaGetSymbolAddress((void**)&QKVl, g_QKVl);

    cudaFuncSetAttribute(k_flash,        cudaFuncAttributeMaxDynamicSharedMemorySize, FLASH_SMEM);
    cudaFuncSetAttribute(mma_gemm<true>, cudaFuncAttributeMaxDynamicSharedMemorySize, GEMM_SMEM);
    cudaFuncSetAttribute(mma_gemm<false>,cudaFuncAttributeMaxDynamicSharedMemorySize, GEMM_SMEM);

    // 1. one fused hi/lo split of all inputs & weights
    k_split_all<<<(N4_TOT + 255)/256, 256>>>(x, wq, wk, wv, wo, Xh, Xl, Wh, Wl, WOh, WOl);

    // 2. fused QKV projection + RoPE + kv-cache outputs + bf16 hi/lo emit
    mma_gemm<true><<<dim3(QKVDIM/128, MTOT/128), 256, GEMM_SMEM>>>(
        Xh, Xl, Wh, Wl, nullptr, 0, HIDDEN, freqs, outk, outv, QKVh, QKVl);

    // 3. fused flash attention -> AOh/AOl
    k_flash<<<dim3(SEQ/128, BATCH*NH), 256, FLASH_SMEM>>>(QKVh, QKVl, AOh, AOl);

    // 4. output projection
    mma_gemm<false><<<dim3(HIDDEN/128, MTOT/128), 256, GEMM_SMEM>>>(
        AOh, AOl, WOh, WOl, out, HIDDEN, QDIM, nullptr, nullptr, nullptr, nullptr, nullptr);
}